// round 1
// baseline (speedup 1.0000x reference)
#include <cuda_runtime.h>
#include <cuda_bf16.h>

// ---------------------------------------------------------------------------
// GraphTransformer: GraphSAGE aggregate + transformer block x (2 layers) + cls
// fp32 baseline. All GEMMs via one tiled SGEMM (NT and NN variants).
// ---------------------------------------------------------------------------

#define NLAY 2
#define HEADS 4
#define CDIM 512
#define INDIM 256
#define FAN 16
#define BSEED 256
#define NCLS 47
#define DHEAD 128

// ---------------- scratch (static device memory; no allocations) -----------
constexpr long SZ_H2  = 65536L * 512;
constexpr long SZ_S1  = 4096L * 512;
constexpr long SZ_S0  = 256L * 512;
constexpr long SZ_CAT = 4096L * 1024;
constexpr long SZ_C   = 4096L * 512;
constexpr long SZ_QKV = 4096L * 1536;
constexpr long SZ_SCO = 4L * 4096L * 4096L;
constexpr long SZ_FFH = 4096L * 1024;

constexpr long OFF_H2   = 0;
constexpr long OFF_S1A  = OFF_H2  + SZ_H2;
constexpr long OFF_S1B  = OFF_S1A + SZ_S1;
constexpr long OFF_S0A  = OFF_S1B + SZ_S1;
constexpr long OFF_S0B  = OFF_S0A + SZ_S0;
constexpr long OFF_CAT  = OFF_S0B + SZ_S0;
constexpr long OFF_TLOC = OFF_CAT + SZ_CAT;
constexpr long OFF_HH   = OFF_TLOC + SZ_C;
constexpr long OFF_QKV  = OFF_HH  + SZ_C;
constexpr long OFF_SCO  = OFF_QKV + SZ_QKV;
constexpr long OFF_ATO  = OFF_SCO + SZ_SCO;
constexpr long OFF_HH2  = OFF_ATO + SZ_C;
constexpr long OFF_FFH  = OFF_HH2 + SZ_C;
constexpr long TOTAL_F  = OFF_FFH + SZ_FFH;

__device__ float g_buf[TOTAL_F];

// ---------------- block reductions -----------------------------------------
__device__ __forceinline__ float block_sum(float v, float* sm) {
    int lane = threadIdx.x & 31, w = threadIdx.x >> 5;
    #pragma unroll
    for (int o = 16; o; o >>= 1) v += __shfl_xor_sync(0xffffffffu, v, o);
    if (lane == 0) sm[w] = v;
    __syncthreads();
    float t = 0.f;
    int nw = blockDim.x >> 5;
    for (int i = 0; i < nw; i++) t += sm[i];
    __syncthreads();
    return t;
}

__device__ __forceinline__ float block_max(float v, float* sm) {
    int lane = threadIdx.x & 31, w = threadIdx.x >> 5;
    #pragma unroll
    for (int o = 16; o; o >>= 1) v = fmaxf(v, __shfl_xor_sync(0xffffffffu, v, o));
    if (lane == 0) sm[w] = v;
    __syncthreads();
    float t = -3.0e38f;
    int nw = blockDim.x >> 5;
    for (int i = 0; i < nw; i++) t = fmaxf(t, sm[i]);
    __syncthreads();
    return t;
}

// ---------------- SGEMM: C = alpha*A*op(B) + bias + res, *rowscale ---------
// TB=true : B is [N,K] row-major (C = A B^T)
// TB=false: B is [K,N] row-major (C = A B)   (requires N % 4 == 0)
// batched via blockIdx.z with element strides sA/sB/sC. K must be % 8 == 0.
template <bool TB>
__global__ __launch_bounds__(256)
void sgemm128(const float* __restrict__ A, const float* __restrict__ B,
              const float* __restrict__ bias, const float* __restrict__ res,
              const float* __restrict__ rowscale, float* __restrict__ C,
              int M, int N, int K, int lda, int ldb, int ldc,
              long sA, long sB, long sC, float alpha, int relu)
{
    __shared__ float As[8][128];
    __shared__ float Bs[8][128];
    A += blockIdx.z * sA;  B += blockIdx.z * sB;  C += blockIdx.z * sC;

    const int tid  = threadIdx.x;
    const int m0   = blockIdx.y * 128;
    const int n0   = blockIdx.x * 128;
    const int lrow = tid >> 1;          // 0..127
    const int lcol = (tid & 1) * 4;     // 0 or 4
    const int bk   = tid >> 5;          // 0..7   (NN B-load row)
    const int bn   = (tid & 31) * 4;    // 0..124 (NN B-load col)
    const int tx   = tid & 15, ty = tid >> 4;

    float acc[8][8];
    #pragma unroll
    for (int i = 0; i < 8; i++)
        #pragma unroll
        for (int j = 0; j < 8; j++) acc[i][j] = 0.f;

    for (int k0 = 0; k0 < K; k0 += 8) {
        float4 av = make_float4(0.f, 0.f, 0.f, 0.f);
        {
            int gm = m0 + lrow;
            if (gm < M)
                av = *reinterpret_cast<const float4*>(&A[(long)gm * lda + k0 + lcol]);
        }
        float4 bv = make_float4(0.f, 0.f, 0.f, 0.f);
        if (TB) {
            int gn = n0 + lrow;
            if (gn < N)
                bv = *reinterpret_cast<const float4*>(&B[(long)gn * ldb + k0 + lcol]);
        } else {
            int gn = n0 + bn;
            if (gn < N)
                bv = *reinterpret_cast<const float4*>(&B[(long)(k0 + bk) * ldb + gn]);
        }
        As[lcol + 0][lrow] = av.x; As[lcol + 1][lrow] = av.y;
        As[lcol + 2][lrow] = av.z; As[lcol + 3][lrow] = av.w;
        if (TB) {
            Bs[lcol + 0][lrow] = bv.x; Bs[lcol + 1][lrow] = bv.y;
            Bs[lcol + 2][lrow] = bv.z; Bs[lcol + 3][lrow] = bv.w;
        } else {
            *reinterpret_cast<float4*>(&Bs[bk][bn]) = bv;
        }
        __syncthreads();

        #pragma unroll
        for (int kk = 0; kk < 8; kk++) {
            float4 a0 = *reinterpret_cast<const float4*>(&As[kk][ty * 8]);
            float4 a1 = *reinterpret_cast<const float4*>(&As[kk][ty * 8 + 4]);
            float4 b0 = *reinterpret_cast<const float4*>(&Bs[kk][tx * 8]);
            float4 b1 = *reinterpret_cast<const float4*>(&Bs[kk][tx * 8 + 4]);
            float ar[8] = {a0.x, a0.y, a0.z, a0.w, a1.x, a1.y, a1.z, a1.w};
            float br[8] = {b0.x, b0.y, b0.z, b0.w, b1.x, b1.y, b1.z, b1.w};
            #pragma unroll
            for (int i = 0; i < 8; i++)
                #pragma unroll
                for (int j = 0; j < 8; j++)
                    acc[i][j] = fmaf(ar[i], br[j], acc[i][j]);
        }
        __syncthreads();
    }

    #pragma unroll
    for (int i = 0; i < 8; i++) {
        int m = m0 + ty * 8 + i;
        if (m >= M) break;
        float rs = rowscale ? rowscale[m] : 1.f;
        #pragma unroll
        for (int j = 0; j < 8; j++) {
            int n = n0 + tx * 8 + j;
            if (n < N) {
                float v = alpha * acc[i][j];
                if (bias) v += bias[n];
                if (res)  v += res[(long)m * ldc + n];
                if (relu) v = fmaxf(v, 0.f);
                C[(long)m * ldc + n] = v * rs;
            }
        }
    }
}

// ---------------- masked-mean aggregate + concat ----------------------------
// cat[i, 0:C]  = sf[i, :]
// cat[i, C:2C] = sum_f child[i*F+f]*m[i,f] / max(sum_f m[i,f], 1)
__global__ void agg_concat(const float* __restrict__ sf,
                           const float* __restrict__ child,
                           const int* __restrict__ nbm,
                           float* __restrict__ cat, int n)
{
    int i = blockIdx.x;
    __shared__ int ms[FAN];
    if (threadIdx.x < FAN) ms[threadIdx.x] = nbm[(long)i * FAN + threadIdx.x];
    __syncthreads();
    float denom = 0.f;
    #pragma unroll
    for (int f = 0; f < FAN; f++) denom += (float)ms[f];
    float inv = 1.f / fmaxf(denom, 1.f);
    for (int c = threadIdx.x; c < CDIM; c += blockDim.x) {
        float acc = 0.f;
        #pragma unroll
        for (int f = 0; f < FAN; f++)
            if (ms[f]) acc += child[((long)i * FAN + f) * CDIM + c];
        cat[(long)i * (2 * CDIM) + c]        = sf[(long)i * CDIM + c];
        cat[(long)i * (2 * CDIM) + CDIM + c] = acc * inv;
    }
}

// ---------------- fused add + LayerNorm ------------------------------------
// y = LN(x + r) * g + b     (row length = 512, 128 threads)
__global__ __launch_bounds__(128)
void ln_add(const float* __restrict__ x, const float* __restrict__ r,
            const float* __restrict__ g, const float* __restrict__ b,
            float* __restrict__ y)
{
    __shared__ float sm[8];
    long row = blockIdx.x;
    int tid = threadIdx.x;
    float4 v = *reinterpret_cast<const float4*>(x + row * CDIM + tid * 4);
    float4 rv = *reinterpret_cast<const float4*>(r + row * CDIM + tid * 4);
    v.x += rv.x; v.y += rv.y; v.z += rv.z; v.w += rv.w;
    float tot = block_sum(v.x + v.y + v.z + v.w, sm);
    float mean = tot * (1.f / CDIM);
    float dx = v.x - mean, dy = v.y - mean, dz = v.z - mean, dw = v.w - mean;
    float var = block_sum(dx * dx + dy * dy + dz * dz + dw * dw, sm) * (1.f / CDIM);
    float rstd = rsqrtf(var + 1e-5f);
    float4 gv = *reinterpret_cast<const float4*>(g + tid * 4);
    float4 bv = *reinterpret_cast<const float4*>(b + tid * 4);
    float4 o;
    o.x = dx * rstd * gv.x + bv.x;
    o.y = dy * rstd * gv.y + bv.y;
    o.z = dz * rstd * gv.z + bv.z;
    o.w = dw * rstd * gv.w + bv.w;
    *reinterpret_cast<float4*>(y + row * CDIM + tid * 4) = o;
}

// ---------------- in-place row softmax -------------------------------------
__global__ __launch_bounds__(256)
void softmax_inplace(float* __restrict__ S, int ncols)
{
    __shared__ float sm[8];
    long row = blockIdx.x;
    float* p = S + row * (long)ncols;
    int tid = threadIdx.x;
    float mx = -3.0e38f;
    for (int c = tid; c < ncols; c += 256) mx = fmaxf(mx, p[c]);
    mx = block_max(mx, sm);
    float sum = 0.f;
    for (int c = tid; c < ncols; c += 256) {
        float e = __expf(p[c] - mx);
        p[c] = e;
        sum += e;
    }
    sum = block_sum(sum, sm);
    float inv = 1.f / sum;
    for (int c = tid; c < ncols; c += 256) p[c] *= inv;
}

// ---------------- host orchestration ---------------------------------------
static inline void gemm_tb(const float* A, const float* B, const float* bias,
                           const float* res, const float* rs, float* C,
                           int M, int N, int K, int lda, int ldb, int ldc,
                           long sA, long sB, long sC, int batch,
                           float alpha, int relu)
{
    dim3 g((N + 127) / 128, (M + 127) / 128, batch);
    sgemm128<true><<<g, 256>>>(A, B, bias, res, rs, C, M, N, K, lda, ldb, ldc,
                               sA, sB, sC, alpha, relu);
}

static inline void gemm_nn(const float* A, const float* B, const float* bias,
                           const float* res, const float* rs, float* C,
                           int M, int N, int K, int lda, int ldb, int ldc,
                           long sA, long sB, long sC, int batch,
                           float alpha, int relu)
{
    dim3 g((N + 127) / 128, (M + 127) / 128, batch);
    sgemm128<false><<<g, 256>>>(A, B, bias, res, rs, C, M, N, K, lda, ldb, ldc,
                                sA, sB, sC, alpha, relu);
}

extern "C" void kernel_launch(void* const* d_in, const int* in_sizes, int n_in,
                              void* d_out, int out_size)
{
    const float* feats0 = (const float*)d_in[0];
    const float* feats1 = (const float*)d_in[1];
    const float* feats2 = (const float*)d_in[2];
    const float* nmask0 = (const float*)d_in[3];
    const float* nmask1 = (const float*)d_in[4];
    const float* nmask2 = (const float*)d_in[5];
    const int*   nbm0   = (const int*)d_in[6];
    const int*   nbm1   = (const int*)d_in[7];
    const float* emb_w  = (const float*)d_in[8];
    const float* emb_b  = (const float*)d_in[9];
    const float* sage_w = (const float*)d_in[10];
    const float* sage_b = (const float*)d_in[11];
    const float* qkv_w  = (const float*)d_in[12];
    const float* qkv_b  = (const float*)d_in[13];
    const float* out_w  = (const float*)d_in[14];
    const float* out_b  = (const float*)d_in[15];
    const float* n1_g   = (const float*)d_in[16];
    const float* n1_b   = (const float*)d_in[17];
    const float* n2_g   = (const float*)d_in[18];
    const float* n2_b   = (const float*)d_in[19];
    const float* ffn_w1 = (const float*)d_in[20];
    const float* ffn_b1 = (const float*)d_in[21];
    const float* ffn_w2 = (const float*)d_in[22];
    const float* ffn_b2 = (const float*)d_in[23];
    const float* cls_w  = (const float*)d_in[24];
    const float* cls_b  = (const float*)d_in[25];
    float* out = (float*)d_out;
    (void)in_sizes; (void)n_in; (void)out_size;

    static float* buf = nullptr;
    if (!buf) cudaGetSymbolAddress((void**)&buf, g_buf);

    float* H2   = buf + OFF_H2;
    float* S1A  = buf + OFF_S1A;
    float* S1B  = buf + OFF_S1B;
    float* S0A  = buf + OFF_S0A;
    float* S0B  = buf + OFF_S0B;
    float* CAT  = buf + OFF_CAT;
    float* TLOC = buf + OFF_TLOC;
    float* HH   = buf + OFF_HH;
    float* QKVb = buf + OFF_QKV;
    float* SCO  = buf + OFF_SCO;
    float* ATO  = buf + OFF_ATO;
    float* HH2  = buf + OFF_HH2;
    float* FFH  = buf + OFF_FFH;

    const float attn_scale = 0.088388347648318447f;  // 1/sqrt(128)

    auto run_block = [&](int li, int n, const float* sf, const float* child,
                         const int* nbm, const float* nmask, float* out_state) {
        // masked-mean aggregation + concat -> CAT [n, 2C]
        agg_concat<<<n, 256>>>(sf, child, nbm, CAT, n);
        // h_local = CAT @ sage_w[li]^T + sage_b[li]
        gemm_tb(CAT, sage_w + (long)li * CDIM * 2 * CDIM, sage_b + li * CDIM,
                nullptr, nullptr, TLOC, n, CDIM, 2 * CDIM,
                2 * CDIM, 2 * CDIM, CDIM, 0, 0, 0, 1, 1.f, 0);
        // h = LN(sf + h_local)
        ln_add<<<n, 128>>>(sf, TLOC, n1_g + li * CDIM, n1_b + li * CDIM, HH);
        // qkv = h @ qkv_w^T + qkv_b   [n, 3C]
        gemm_tb(HH, qkv_w + (long)li * 3 * CDIM * CDIM, qkv_b + li * 3 * CDIM,
                nullptr, nullptr, QKVb, n, 3 * CDIM, CDIM,
                CDIM, CDIM, 3 * CDIM, 0, 0, 0, 1, 1.f, 0);
        // S[h] = scale * Q_h K_h^T   (batched over heads via grid.z)
        gemm_tb(QKVb, QKVb + CDIM, nullptr, nullptr, nullptr, SCO,
                n, n, DHEAD, 3 * CDIM, 3 * CDIM, n,
                DHEAD, DHEAD, (long)n * n, HEADS, attn_scale, 0);
        softmax_inplace<<<HEADS * n, 256>>>(SCO, n);
        // O[:, h*DH:(h+1)*DH] = P_h @ V_h  (NN)
        gemm_nn(SCO, QKVb + 2 * CDIM, nullptr, nullptr, nullptr, ATO,
                n, DHEAD, n, n, 3 * CDIM, CDIM,
                (long)n * n, DHEAD, DHEAD, HEADS, 1.f, 0);
        // attn = O @ out_w^T + out_b
        gemm_tb(ATO, out_w + (long)li * CDIM * CDIM, out_b + li * CDIM,
                nullptr, nullptr, TLOC, n, CDIM, CDIM,
                CDIM, CDIM, CDIM, 0, 0, 0, 1, 1.f, 0);
        // h2 = LN(h + attn)
        ln_add<<<n, 128>>>(HH, TLOC, n2_g + li * CDIM, n2_b + li * CDIM, HH2);
        // hid = relu(h2 @ w1^T + b1)
        gemm_tb(HH2, ffn_w1 + (long)li * 2 * CDIM * CDIM, ffn_b1 + li * 2 * CDIM,
                nullptr, nullptr, FFH, n, 2 * CDIM, CDIM,
                CDIM, CDIM, 2 * CDIM, 0, 0, 0, 1, 1.f, 1);
        // out_state = (h2 + hid @ w2^T + b2) * nmask
        gemm_tb(FFH, ffn_w2 + (long)li * CDIM * 2 * CDIM, ffn_b2 + li * CDIM,
                HH2, nmask, out_state, n, CDIM, 2 * CDIM,
                2 * CDIM, 2 * CDIM, CDIM, 0, 0, 0, 1, 1.f, 0);
    };

    // embeddings: state = (feats @ emb_w^T + emb_b) * nmask
    gemm_tb(feats2, emb_w, emb_b, nullptr, nmask2, H2,
            65536, CDIM, INDIM, INDIM, INDIM, CDIM, 0, 0, 0, 1, 1.f, 0);
    gemm_tb(feats1, emb_w, emb_b, nullptr, nmask1, S1A,
            4096, CDIM, INDIM, INDIM, INDIM, CDIM, 0, 0, 0, 1, 1.f, 0);
    gemm_tb(feats0, emb_w, emb_b, nullptr, nmask0, S0A,
            256, CDIM, INDIM, INDIM, INDIM, CDIM, 0, 0, 0, 1, 1.f, 0);

    // layer 0: depth 1 (uses old s2), then depth 0 (uses OLD s1)
    run_block(0, 4096, S1A, H2,  nbm1, nmask1, S1B);
    run_block(0, 256,  S0A, S1A, nbm0, nmask0, S0B);
    // layer 1: depth 0 (uses updated s1)
    run_block(1, 256,  S0B, S1B, nbm0, nmask0, S0A);

    // classifier
    gemm_tb(S0A, cls_w, cls_b, nullptr, nullptr, out,
            BSEED, NCLS, CDIM, CDIM, CDIM, NCLS, 0, 0, 0, 1, 1.f, 0);
}

// round 2
// speedup vs baseline: 1.7747x; 1.7747x over previous
#include <cuda_runtime.h>
#include <cuda_bf16.h>
#include <mma.h>

using namespace nvcuda;

// ---------------------------------------------------------------------------
// GraphTransformer — tf32 tensor-core GEMMs + light fused elementwise kernels
// ---------------------------------------------------------------------------

#define NLAY 2
#define HEADS 4
#define CDIM 512
#define INDIM 256
#define FAN 16
#define BSEED 256
#define NCLS 47
#define DHEAD 128

// ---------------- scratch (static device memory; no allocations) -----------
constexpr long SZ_H2  = 65536L * 512;
constexpr long SZ_S1  = 4096L * 512;
constexpr long SZ_S0  = 256L * 512;
constexpr long SZ_CAT = 4096L * 1024;
constexpr long SZ_C   = 4096L * 512;
constexpr long SZ_QKV = 4096L * 1536;
constexpr long SZ_SCO = 4L * 4096L * 4096L;
constexpr long SZ_FFH = 4096L * 1024;

constexpr long OFF_H2   = 0;
constexpr long OFF_S1A  = OFF_H2  + SZ_H2;
constexpr long OFF_S1B  = OFF_S1A + SZ_S1;
constexpr long OFF_S0A  = OFF_S1B + SZ_S1;
constexpr long OFF_S0B  = OFF_S0A + SZ_S0;
constexpr long OFF_CAT  = OFF_S0B + SZ_S0;
constexpr long OFF_TLOC = OFF_CAT + SZ_CAT;
constexpr long OFF_HH   = OFF_TLOC + SZ_C;
constexpr long OFF_QKV  = OFF_HH  + SZ_C;
constexpr long OFF_SCO  = OFF_QKV + SZ_QKV;
constexpr long OFF_ATO  = OFF_SCO + SZ_SCO;
constexpr long OFF_HH2  = OFF_ATO + SZ_C;
constexpr long OFF_FFH  = OFF_HH2 + SZ_C;
constexpr long TOTAL_F  = OFF_FFH + SZ_FFH;

__device__ float g_buf[TOTAL_F];

// ---------------- block reductions -----------------------------------------
__device__ __forceinline__ float block_sum(float v, float* sm) {
    int lane = threadIdx.x & 31, w = threadIdx.x >> 5;
    #pragma unroll
    for (int o = 16; o; o >>= 1) v += __shfl_xor_sync(0xffffffffu, v, o);
    if (lane == 0) sm[w] = v;
    __syncthreads();
    float t = 0.f;
    int nw = blockDim.x >> 5;
    for (int i = 0; i < nw; i++) t += sm[i];
    __syncthreads();
    return t;
}

__device__ __forceinline__ float block_max(float v, float* sm) {
    int lane = threadIdx.x & 31, w = threadIdx.x >> 5;
    #pragma unroll
    for (int o = 16; o; o >>= 1) v = fmaxf(v, __shfl_xor_sync(0xffffffffu, v, o));
    if (lane == 0) sm[w] = v;
    __syncthreads();
    float t = -3.0e38f;
    int nw = blockDim.x >> 5;
    for (int i = 0; i < nw; i++) t = fmaxf(t, sm[i]);
    __syncthreads();
    return t;
}

// ---------------- tf32 tensor-core GEMM -------------------------------------
// C = A * op(B).  TB=true: B is [N,K] row-major (C = A B^T).
//                 TB=false: B is [K,N] row-major (C = A B).
// Requires: M % 128 == 0, N % 128 == 0, K % 16 == 0. float4-aligned pointers.
// Batched over blockIdx.z with element strides sA/sB/sC.
template <bool TB>
__global__ __launch_bounds__(256)
void tgemm128(const float* __restrict__ A, const float* __restrict__ B,
              float* __restrict__ C, int M, int N, int K,
              int lda, int ldb, int ldc, long sA, long sB, long sC)
{
    __shared__ float As[128][20];
    __shared__ float Bsm[2560];     // TB view: [128][20]; NN view: [16][132]

    A += blockIdx.z * sA;  B += blockIdx.z * sB;  C += blockIdx.z * sC;

    const int tid = threadIdx.x;
    const int m0  = blockIdx.y * 128;
    const int n0  = blockIdx.x * 128;
    const int wid = tid >> 5;
    const int wm  = wid >> 2;        // 0..1  (64-row slab)
    const int wn  = wid & 3;         // 0..3  (32-col slab)

    wmma::fragment<wmma::accumulator, 16, 16, 8, float> cf[4][2];
    #pragma unroll
    for (int m = 0; m < 4; m++)
        #pragma unroll
        for (int n = 0; n < 2; n++) wmma::fill_fragment(cf[m][n], 0.f);

    for (int k0 = 0; k0 < K; k0 += 16) {
        // ---- load A tile 128x16 ----
        #pragma unroll
        for (int i = 0; i < 2; i++) {
            int li = tid + i * 256;
            int r = li >> 2, c4 = (li & 3) * 4;
            float4 v = *reinterpret_cast<const float4*>(
                &A[(long)(m0 + r) * lda + k0 + c4]);
            float4 t;
            t.x = wmma::__float_to_tf32(v.x);
            t.y = wmma::__float_to_tf32(v.y);
            t.z = wmma::__float_to_tf32(v.z);
            t.w = wmma::__float_to_tf32(v.w);
            *reinterpret_cast<float4*>(&As[r][c4]) = t;
        }
        // ---- load B tile ----
        if (TB) {
            float (*Bt)[20] = reinterpret_cast<float (*)[20]>(Bsm);
            #pragma unroll
            for (int i = 0; i < 2; i++) {
                int li = tid + i * 256;
                int r = li >> 2, c4 = (li & 3) * 4;
                float4 v = *reinterpret_cast<const float4*>(
                    &B[(long)(n0 + r) * ldb + k0 + c4]);
                float4 t;
                t.x = wmma::__float_to_tf32(v.x);
                t.y = wmma::__float_to_tf32(v.y);
                t.z = wmma::__float_to_tf32(v.z);
                t.w = wmma::__float_to_tf32(v.w);
                *reinterpret_cast<float4*>(&Bt[r][c4]) = t;
            }
        } else {
            float (*Bn)[132] = reinterpret_cast<float (*)[132]>(Bsm);
            #pragma unroll
            for (int i = 0; i < 2; i++) {
                int li = tid + i * 256;
                int r = li >> 5, c4 = (li & 31) * 4;
                float4 v = *reinterpret_cast<const float4*>(
                    &B[(long)(k0 + r) * ldb + n0 + c4]);
                float4 t;
                t.x = wmma::__float_to_tf32(v.x);
                t.y = wmma::__float_to_tf32(v.y);
                t.z = wmma::__float_to_tf32(v.z);
                t.w = wmma::__float_to_tf32(v.w);
                *reinterpret_cast<float4*>(&Bn[r][c4]) = t;
            }
        }
        __syncthreads();

        #pragma unroll
        for (int kk = 0; kk < 16; kk += 8) {
            wmma::fragment<wmma::matrix_a, 16, 16, 8,
                           wmma::precision::tf32, wmma::row_major> af[4];
            #pragma unroll
            for (int m = 0; m < 4; m++)
                wmma::load_matrix_sync(af[m], &As[wm * 64 + m * 16][kk], 20);

            if constexpr (TB) {
                wmma::fragment<wmma::matrix_b, 16, 16, 8,
                               wmma::precision::tf32, wmma::col_major> bf[2];
                float (*Bt)[20] = reinterpret_cast<float (*)[20]>(Bsm);
                #pragma unroll
                for (int n = 0; n < 2; n++)
                    wmma::load_matrix_sync(bf[n], &Bt[wn * 32 + n * 16][kk], 20);
                #pragma unroll
                for (int m = 0; m < 4; m++)
                    #pragma unroll
                    for (int n = 0; n < 2; n++)
                        wmma::mma_sync(cf[m][n], af[m], bf[n], cf[m][n]);
            } else {
                wmma::fragment<wmma::matrix_b, 16, 16, 8,
                               wmma::precision::tf32, wmma::row_major> bf[2];
                float (*Bn)[132] = reinterpret_cast<float (*)[132]>(Bsm);
                #pragma unroll
                for (int n = 0; n < 2; n++)
                    wmma::load_matrix_sync(bf[n], &Bn[kk][wn * 32 + n * 16], 132);
                #pragma unroll
                for (int m = 0; m < 4; m++)
                    #pragma unroll
                    for (int n = 0; n < 2; n++)
                        wmma::mma_sync(cf[m][n], af[m], bf[n], cf[m][n]);
            }
        }
        __syncthreads();
    }

    #pragma unroll
    for (int m = 0; m < 4; m++)
        #pragma unroll
        for (int n = 0; n < 2; n++)
            wmma::store_matrix_sync(
                &C[(long)(m0 + wm * 64 + m * 16) * ldc + n0 + wn * 32 + n * 16],
                cf[m][n], ldc, wmma::mem_row_major);
}

// ---------------- fp32 SGEMM (classifier only: N=47) ------------------------
__global__ __launch_bounds__(256)
void sgemm_cls(const float* __restrict__ A, const float* __restrict__ B,
               const float* __restrict__ bias, float* __restrict__ C,
               int M, int N, int K)
{
    // one thread per output element; M=256, N=47, K=512 -> 12K threads
    int m = blockIdx.y * blockDim.y + threadIdx.y;
    int n = blockIdx.x * blockDim.x + threadIdx.x;
    if (m >= M || n >= N) return;
    const float* a = A + (long)m * K;
    const float* b = B + (long)n * K;
    float acc = 0.f;
    for (int k = 0; k < K; k += 4) {
        float4 av = *reinterpret_cast<const float4*>(a + k);
        float4 bv = *reinterpret_cast<const float4*>(b + k);
        acc = fmaf(av.x, bv.x, acc);
        acc = fmaf(av.y, bv.y, acc);
        acc = fmaf(av.z, bv.z, acc);
        acc = fmaf(av.w, bv.w, acc);
    }
    C[(long)m * N + n] = acc + bias[n];
}

// ---------------- elementwise epilogue --------------------------------------
// C = (C (+bias) (+res)) (relu?) * rowscale        one block per row
__global__ __launch_bounds__(128)
void epilogue(float* __restrict__ C, const float* __restrict__ bias,
              const float* __restrict__ res, const float* __restrict__ rowscale,
              int ncol4, int relu)
{
    long row = blockIdx.x;
    float rs = rowscale ? rowscale[row] : 1.f;
    float4* c = reinterpret_cast<float4*>(C + row * (long)ncol4 * 4);
    const float4* r4 = res ? reinterpret_cast<const float4*>(res + row * (long)ncol4 * 4)
                           : nullptr;
    const float4* b4 = bias ? reinterpret_cast<const float4*>(bias) : nullptr;
    for (int i = threadIdx.x; i < ncol4; i += blockDim.x) {
        float4 v = c[i];
        if (b4) { float4 b = b4[i]; v.x += b.x; v.y += b.y; v.z += b.z; v.w += b.w; }
        if (r4) { float4 r = r4[i]; v.x += r.x; v.y += r.y; v.z += r.z; v.w += r.w; }
        if (relu) {
            v.x = fmaxf(v.x, 0.f); v.y = fmaxf(v.y, 0.f);
            v.z = fmaxf(v.z, 0.f); v.w = fmaxf(v.w, 0.f);
        }
        v.x *= rs; v.y *= rs; v.z *= rs; v.w *= rs;
        c[i] = v;
    }
}

// ---------------- masked-mean aggregate + concat ----------------------------
__global__ void agg_concat(const float* __restrict__ sf,
                           const float* __restrict__ child,
                           const int* __restrict__ nbm,
                           float* __restrict__ cat, int n)
{
    int i = blockIdx.x;
    __shared__ int ms[FAN];
    if (threadIdx.x < FAN) ms[threadIdx.x] = nbm[(long)i * FAN + threadIdx.x];
    __syncthreads();
    float denom = 0.f;
    #pragma unroll
    for (int f = 0; f < FAN; f++) denom += (float)ms[f];
    float inv = 1.f / fmaxf(denom, 1.f);
    for (int c = threadIdx.x; c < CDIM; c += blockDim.x) {
        float acc = 0.f;
        #pragma unroll
        for (int f = 0; f < FAN; f++)
            if (ms[f]) acc += child[((long)i * FAN + f) * CDIM + c];
        cat[(long)i * (2 * CDIM) + c]        = sf[(long)i * CDIM + c];
        cat[(long)i * (2 * CDIM) + CDIM + c] = acc * inv;
    }
}

// ---------------- fused add + LayerNorm -------------------------------------
__global__ __launch_bounds__(128)
void ln_add(const float* __restrict__ x, const float* __restrict__ r,
            const float* __restrict__ g, const float* __restrict__ b,
            float* __restrict__ y)
{
    __shared__ float sm[8];
    long row = blockIdx.x;
    int tid = threadIdx.x;
    float4 v = *reinterpret_cast<const float4*>(x + row * CDIM + tid * 4);
    float4 rv = *reinterpret_cast<const float4*>(r + row * CDIM + tid * 4);
    v.x += rv.x; v.y += rv.y; v.z += rv.z; v.w += rv.w;
    float tot = block_sum(v.x + v.y + v.z + v.w, sm);
    float mean = tot * (1.f / CDIM);
    float dx = v.x - mean, dy = v.y - mean, dz = v.z - mean, dw = v.w - mean;
    float var = block_sum(dx * dx + dy * dy + dz * dz + dw * dw, sm) * (1.f / CDIM);
    float rstd = rsqrtf(var + 1e-5f);
    float4 gv = *reinterpret_cast<const float4*>(g + tid * 4);
    float4 bv = *reinterpret_cast<const float4*>(b + tid * 4);
    float4 o;
    o.x = dx * rstd * gv.x + bv.x;
    o.y = dy * rstd * gv.y + bv.y;
    o.z = dz * rstd * gv.z + bv.z;
    o.w = dw * rstd * gv.w + bv.w;
    *reinterpret_cast<float4*>(y + row * CDIM + tid * 4) = o;
}

// ---------------- in-place row softmax (with score scale) -------------------
__global__ __launch_bounds__(256)
void softmax_inplace(float* __restrict__ S, int ncols, float scale)
{
    __shared__ float sm[8];
    long row = blockIdx.x;
    float* p = S + row * (long)ncols;
    int tid = threadIdx.x;
    float mx = -3.0e38f;
    for (int c = tid; c < ncols; c += 256) mx = fmaxf(mx, p[c] * scale);
    mx = block_max(mx, sm);
    float sum = 0.f;
    for (int c = tid; c < ncols; c += 256) {
        float e = __expf(p[c] * scale - mx);
        p[c] = e;
        sum += e;
    }
    sum = block_sum(sum, sm);
    float inv = 1.f / sum;
    for (int c = tid; c < ncols; c += 256) p[c] *= inv;
}

// ---------------- host helpers ----------------------------------------------
static inline void tg_tb(const float* A, const float* B, float* C,
                         int M, int N, int K, int lda, int ldb, int ldc,
                         long sA = 0, long sB = 0, long sC = 0, int batch = 1)
{
    dim3 g(N / 128, M / 128, batch);
    tgemm128<true><<<g, 256>>>(A, B, C, M, N, K, lda, ldb, ldc, sA, sB, sC);
}

static inline void tg_nn(const float* A, const float* B, float* C,
                         int M, int N, int K, int lda, int ldb, int ldc,
                         long sA = 0, long sB = 0, long sC = 0, int batch = 1)
{
    dim3 g(N / 128, M / 128, batch);
    tgemm128<false><<<g, 256>>>(A, B, C, M, N, K, lda, ldb, ldc, sA, sB, sC);
}

extern "C" void kernel_launch(void* const* d_in, const int* in_sizes, int n_in,
                              void* d_out, int out_size)
{
    const float* feats0 = (const float*)d_in[0];
    const float* feats1 = (const float*)d_in[1];
    const float* feats2 = (const float*)d_in[2];
    const float* nmask0 = (const float*)d_in[3];
    const float* nmask1 = (const float*)d_in[4];
    const float* nmask2 = (const float*)d_in[5];
    const int*   nbm0   = (const int*)d_in[6];
    const int*   nbm1   = (const int*)d_in[7];
    const float* emb_w  = (const float*)d_in[8];
    const float* emb_b  = (const float*)d_in[9];
    const float* sage_w = (const float*)d_in[10];
    const float* sage_b = (const float*)d_in[11];
    const float* qkv_w  = (const float*)d_in[12];
    const float* qkv_b  = (const float*)d_in[13];
    const float* out_w  = (const float*)d_in[14];
    const float* out_b  = (const float*)d_in[15];
    const float* n1_g   = (const float*)d_in[16];
    const float* n1_b   = (const float*)d_in[17];
    const float* n2_g   = (const float*)d_in[18];
    const float* n2_b   = (const float*)d_in[19];
    const float* ffn_w1 = (const float*)d_in[20];
    const float* ffn_b1 = (const float*)d_in[21];
    const float* ffn_w2 = (const float*)d_in[22];
    const float* ffn_b2 = (const float*)d_in[23];
    const float* cls_w  = (const float*)d_in[24];
    const float* cls_b  = (const float*)d_in[25];
    float* out = (float*)d_out;
    (void)in_sizes; (void)n_in; (void)out_size;

    static float* buf = nullptr;
    if (!buf) cudaGetSymbolAddress((void**)&buf, g_buf);

    float* H2   = buf + OFF_H2;
    float* S1A  = buf + OFF_S1A;
    float* S1B  = buf + OFF_S1B;
    float* S0A  = buf + OFF_S0A;
    float* S0B  = buf + OFF_S0B;
    float* CAT  = buf + OFF_CAT;
    float* TLOC = buf + OFF_TLOC;
    float* HH   = buf + OFF_HH;
    float* QKVb = buf + OFF_QKV;
    float* SCO  = buf + OFF_SCO;
    float* ATO  = buf + OFF_ATO;
    float* HH2  = buf + OFF_HH2;
    float* FFH  = buf + OFF_FFH;

    const float attn_scale = 0.088388347648318447f;  // 1/sqrt(128)

    auto run_block = [&](int li, int n, const float* sf, const float* child,
                         const int* nbm, const float* nmask, float* out_state) {
        // masked-mean aggregation + concat -> CAT [n, 2C]
        agg_concat<<<n, 256>>>(sf, child, nbm, CAT, n);
        // h_local = CAT @ sage_w[li]^T + sage_b[li]
        tg_tb(CAT, sage_w + (long)li * CDIM * 2 * CDIM, TLOC,
              n, CDIM, 2 * CDIM, 2 * CDIM, 2 * CDIM, CDIM);
        epilogue<<<n, 128>>>(TLOC, sage_b + li * CDIM, nullptr, nullptr, CDIM / 4, 0);
        // h = LN(sf + h_local)
        ln_add<<<n, 128>>>(sf, TLOC, n1_g + li * CDIM, n1_b + li * CDIM, HH);
        // qkv = h @ qkv_w^T + qkv_b   [n, 3C]
        tg_tb(HH, qkv_w + (long)li * 3 * CDIM * CDIM, QKVb,
              n, 3 * CDIM, CDIM, CDIM, CDIM, 3 * CDIM);
        epilogue<<<n, 128>>>(QKVb, qkv_b + li * 3 * CDIM, nullptr, nullptr,
                             3 * CDIM / 4, 0);
        // S[h] = Q_h K_h^T  (scale folded into softmax)
        tg_tb(QKVb, QKVb + CDIM, SCO, n, n, DHEAD,
              3 * CDIM, 3 * CDIM, n, DHEAD, DHEAD, (long)n * n, HEADS);
        softmax_inplace<<<HEADS * n, 256>>>(SCO, n, attn_scale);
        // O[:, h*DH:(h+1)*DH] = P_h @ V_h
        tg_nn(SCO, QKVb + 2 * CDIM, ATO, n, DHEAD, n,
              n, 3 * CDIM, CDIM, (long)n * n, DHEAD, DHEAD, HEADS);
        // attn = O @ out_w^T + out_b
        tg_tb(ATO, out_w + (long)li * CDIM * CDIM, TLOC,
              n, CDIM, CDIM, CDIM, CDIM, CDIM);
        epilogue<<<n, 128>>>(TLOC, out_b + li * CDIM, nullptr, nullptr, CDIM / 4, 0);
        // h2 = LN(h + attn)
        ln_add<<<n, 128>>>(HH, TLOC, n2_g + li * CDIM, n2_b + li * CDIM, HH2);
        // hid = relu(h2 @ w1^T + b1)
        tg_tb(HH2, ffn_w1 + (long)li * 2 * CDIM * CDIM, FFH,
              n, 2 * CDIM, CDIM, CDIM, CDIM, 2 * CDIM);
        epilogue<<<n, 128>>>(FFH, ffn_b1 + li * 2 * CDIM, nullptr, nullptr,
                             2 * CDIM / 4, 1);
        // out_state = (h2 + hid @ w2^T + b2) * nmask
        tg_tb(FFH, ffn_w2 + (long)li * CDIM * 2 * CDIM, out_state,
              n, CDIM, 2 * CDIM, 2 * CDIM, 2 * CDIM, CDIM);
        epilogue<<<n, 128>>>(out_state, ffn_b2 + li * CDIM, HH2, nmask, CDIM / 4, 0);
    };

    // embeddings: state = (feats @ emb_w^T + emb_b) * nmask
    tg_tb(feats2, emb_w, H2, 65536, CDIM, INDIM, INDIM, INDIM, CDIM);
    epilogue<<<65536, 128>>>(H2, emb_b, nullptr, nmask2, CDIM / 4, 0);
    tg_tb(feats1, emb_w, S1A, 4096, CDIM, INDIM, INDIM, INDIM, CDIM);
    epilogue<<<4096, 128>>>(S1A, emb_b, nullptr, nmask1, CDIM / 4, 0);
    tg_tb(feats0, emb_w, S0A, 256, CDIM, INDIM, INDIM, INDIM, CDIM);
    epilogue<<<256, 128>>>(S0A, emb_b, nullptr, nmask0, CDIM / 4, 0);

    // layer 0: depth 1 (uses old s2), then depth 0 (uses OLD s1)
    run_block(0, 4096, S1A, H2,  nbm1, nmask1, S1B);
    run_block(0, 256,  S0A, S1A, nbm0, nmask0, S0B);
    // layer 1: depth 0 (uses updated s1)
    run_block(1, 256,  S0B, S1B, nbm0, nmask0, S0A);

    // classifier (fp32, tiny)
    {
        dim3 b(16, 16), g((NCLS + 15) / 16, (BSEED + 15) / 16);
        sgemm_cls<<<g, b>>>(S0A, cls_w, cls_b, out, BSEED, NCLS, CDIM);
    }
}

// round 3
// speedup vs baseline: 1.8147x; 1.0225x over previous
#include <cuda_runtime.h>
#include <cuda_bf16.h>
#include <mma.h>

using namespace nvcuda;

// ---------------------------------------------------------------------------
// GraphTransformer — tf32 tensor-core GEMMs (BK=32, register double-buffered)
// ---------------------------------------------------------------------------

#define NLAY 2
#define HEADS 4
#define CDIM 512
#define INDIM 256
#define FAN 16
#define BSEED 256
#define NCLS 47
#define DHEAD 128

// ---------------- scratch (static device memory; no allocations) -----------
constexpr long SZ_H2  = 65536L * 512;
constexpr long SZ_S1  = 4096L * 512;
constexpr long SZ_S0  = 256L * 512;
constexpr long SZ_CAT = 4096L * 1024;
constexpr long SZ_C   = 4096L * 512;
constexpr long SZ_QKV = 4096L * 1536;
constexpr long SZ_SCO = 4L * 4096L * 4096L;
constexpr long SZ_FFH = 4096L * 1024;

constexpr long OFF_H2   = 0;
constexpr long OFF_S1A  = OFF_H2  + SZ_H2;
constexpr long OFF_S1B  = OFF_S1A + SZ_S1;
constexpr long OFF_S0A  = OFF_S1B + SZ_S1;
constexpr long OFF_S0B  = OFF_S0A + SZ_S0;
constexpr long OFF_CAT  = OFF_S0B + SZ_S0;
constexpr long OFF_TLOC = OFF_CAT + SZ_CAT;
constexpr long OFF_HH   = OFF_TLOC + SZ_C;
constexpr long OFF_QKV  = OFF_HH  + SZ_C;
constexpr long OFF_SCO  = OFF_QKV + SZ_QKV;
constexpr long OFF_ATO  = OFF_SCO + SZ_SCO;
constexpr long OFF_HH2  = OFF_ATO + SZ_C;
constexpr long OFF_FFH  = OFF_HH2 + SZ_C;
constexpr long TOTAL_F  = OFF_FFH + SZ_FFH;

__device__ float g_buf[TOTAL_F];

// ---------------- block reductions -----------------------------------------
__device__ __forceinline__ float block_sum(float v, float* sm) {
    int lane = threadIdx.x & 31, w = threadIdx.x >> 5;
    #pragma unroll
    for (int o = 16; o; o >>= 1) v += __shfl_xor_sync(0xffffffffu, v, o);
    if (lane == 0) sm[w] = v;
    __syncthreads();
    float t = 0.f;
    int nw = blockDim.x >> 5;
    for (int i = 0; i < nw; i++) t += sm[i];
    __syncthreads();
    return t;
}

__device__ __forceinline__ float block_max(float v, float* sm) {
    int lane = threadIdx.x & 31, w = threadIdx.x >> 5;
    #pragma unroll
    for (int o = 16; o; o >>= 1) v = fmaxf(v, __shfl_xor_sync(0xffffffffu, v, o));
    if (lane == 0) sm[w] = v;
    __syncthreads();
    float t = -3.0e38f;
    int nw = blockDim.x >> 5;
    for (int i = 0; i < nw; i++) t = fmaxf(t, sm[i]);
    __syncthreads();
    return t;
}

__device__ __forceinline__ float4 cvt_tf32_4(float4 v) {
    float4 t;
    t.x = wmma::__float_to_tf32(v.x);
    t.y = wmma::__float_to_tf32(v.y);
    t.z = wmma::__float_to_tf32(v.z);
    t.w = wmma::__float_to_tf32(v.w);
    return t;
}

// ---------------- tf32 tensor-core GEMM, BK=32, reg double-buffer ----------
// C = A * op(B).  TB=true: B is [N,K] row-major (C = A B^T).
//                 TB=false: B is [K,N] row-major (C = A B).
// Requires: M % 128 == 0, N % 128 == 0, K % 32 == 0, float4-aligned pointers.
// Batched over blockIdx.z with element strides sA/sB/sC.
template <bool TB>
__global__ __launch_bounds__(256)
void tgemm128(const float* __restrict__ A, const float* __restrict__ B,
              float* __restrict__ C, int M, int N, int K,
              int lda, int ldb, int ldc, long sA, long sB, long sC)
{
    __shared__ float As[128][36];       // 128 rows x 32 k (pad 4)
    __shared__ float Bsm[4608];         // TB: [128][36];  NN: [32][136]

    A += blockIdx.z * sA;  B += blockIdx.z * sB;  C += blockIdx.z * sC;

    const int tid = threadIdx.x;
    const int m0  = blockIdx.y * 128;
    const int n0  = blockIdx.x * 128;
    const int wid = tid >> 5;
    const int wm  = wid >> 2;        // 0..1  (64-row slab)
    const int wn  = wid & 3;         // 0..3  (32-col slab)

    // per-thread load coordinates (4 x float4 per matrix per tile)
    // A/TB-B tile: 128 x 32  -> li = tid + i*256 : r = li>>3, c = (li&7)*4
    // NN-B tile:   32 x 128  -> r = li>>5, c = (li&31)*4
    const int a_r[4] = { (tid + 0) >> 3, (tid + 256) >> 3,
                         (tid + 512) >> 3, (tid + 768) >> 3 };
    const int a_c   = (tid & 7) * 4;
    const int bn_r[4] = { (tid + 0) >> 5, (tid + 256) >> 5,
                          (tid + 512) >> 5, (tid + 768) >> 5 };
    const int bn_c  = (tid & 31) * 4;

    wmma::fragment<wmma::accumulator, 16, 16, 8, float> cf[4][2];
    #pragma unroll
    for (int m = 0; m < 4; m++)
        #pragma unroll
        for (int n = 0; n < 2; n++) wmma::fill_fragment(cf[m][n], 0.f);

    float4 pa[4], pb[4];

    auto ld_tile = [&](int k0, float4* ra, float4* rb) {
        #pragma unroll
        for (int i = 0; i < 4; i++)
            ra[i] = *reinterpret_cast<const float4*>(
                &A[(long)(m0 + a_r[i]) * lda + k0 + a_c]);
        if (TB) {
            #pragma unroll
            for (int i = 0; i < 4; i++)
                rb[i] = *reinterpret_cast<const float4*>(
                    &B[(long)(n0 + a_r[i]) * ldb + k0 + a_c]);
        } else {
            #pragma unroll
            for (int i = 0; i < 4; i++)
                rb[i] = *reinterpret_cast<const float4*>(
                    &B[(long)(k0 + bn_r[i]) * ldb + n0 + bn_c]);
        }
    };

    auto st_tile = [&](const float4* ra, const float4* rb) {
        #pragma unroll
        for (int i = 0; i < 4; i++)
            *reinterpret_cast<float4*>(&As[a_r[i]][a_c]) = cvt_tf32_4(ra[i]);
        if (TB) {
            float (*Bt)[36] = reinterpret_cast<float (*)[36]>(Bsm);
            #pragma unroll
            for (int i = 0; i < 4; i++)
                *reinterpret_cast<float4*>(&Bt[a_r[i]][a_c]) = cvt_tf32_4(rb[i]);
        } else {
            float (*Bn)[136] = reinterpret_cast<float (*)[136]>(Bsm);
            #pragma unroll
            for (int i = 0; i < 4; i++)
                *reinterpret_cast<float4*>(&Bn[bn_r[i]][bn_c]) = cvt_tf32_4(rb[i]);
        }
    };

    // prologue
    ld_tile(0, pa, pb);
    st_tile(pa, pb);
    __syncthreads();

    for (int k0 = 0; k0 < K; k0 += 32) {
        const bool more = (k0 + 32) < K;
        if (more) ld_tile(k0 + 32, pa, pb);     // prefetch next tile -> regs

        #pragma unroll
        for (int kk = 0; kk < 32; kk += 8) {
            wmma::fragment<wmma::matrix_a, 16, 16, 8,
                           wmma::precision::tf32, wmma::row_major> af[4];
            #pragma unroll
            for (int m = 0; m < 4; m++)
                wmma::load_matrix_sync(af[m], &As[wm * 64 + m * 16][kk], 36);

            if constexpr (TB) {
                wmma::fragment<wmma::matrix_b, 16, 16, 8,
                               wmma::precision::tf32, wmma::col_major> bf[2];
                float (*Bt)[36] = reinterpret_cast<float (*)[36]>(Bsm);
                #pragma unroll
                for (int n = 0; n < 2; n++)
                    wmma::load_matrix_sync(bf[n], &Bt[wn * 32 + n * 16][kk], 36);
                #pragma unroll
                for (int m = 0; m < 4; m++)
                    #pragma unroll
                    for (int n = 0; n < 2; n++)
                        wmma::mma_sync(cf[m][n], af[m], bf[n], cf[m][n]);
            } else {
                wmma::fragment<wmma::matrix_b, 16, 16, 8,
                               wmma::precision::tf32, wmma::row_major> bf[2];
                float (*Bn)[136] = reinterpret_cast<float (*)[136]>(Bsm);
                #pragma unroll
                for (int n = 0; n < 2; n++)
                    wmma::load_matrix_sync(bf[n], &Bn[kk][wn * 32 + n * 16], 136);
                #pragma unroll
                for (int m = 0; m < 4; m++)
                    #pragma unroll
                    for (int n = 0; n < 2; n++)
                        wmma::mma_sync(cf[m][n], af[m], bf[n], cf[m][n]);
            }
        }
        __syncthreads();
        if (more) {
            st_tile(pa, pb);
            __syncthreads();
        }
    }

    #pragma unroll
    for (int m = 0; m < 4; m++)
        #pragma unroll
        for (int n = 0; n < 2; n++)
            wmma::store_matrix_sync(
                &C[(long)(m0 + wm * 64 + m * 16) * ldc + n0 + wn * 32 + n * 16],
                cf[m][n], ldc, wmma::mem_row_major);
}

// ---------------- fp32 SGEMM (classifier only: N=47) ------------------------
__global__ __launch_bounds__(256)
void sgemm_cls(const float* __restrict__ A, const float* __restrict__ B,
               const float* __restrict__ bias, float* __restrict__ C,
               int M, int N, int K)
{
    int m = blockIdx.y * blockDim.y + threadIdx.y;
    int n = blockIdx.x * blockDim.x + threadIdx.x;
    if (m >= M || n >= N) return;
    const float* a = A + (long)m * K;
    const float* b = B + (long)n * K;
    float acc = 0.f;
    for (int k = 0; k < K; k += 4) {
        float4 av = *reinterpret_cast<const float4*>(a + k);
        float4 bv = *reinterpret_cast<const float4*>(b + k);
        acc = fmaf(av.x, bv.x, acc);
        acc = fmaf(av.y, bv.y, acc);
        acc = fmaf(av.z, bv.z, acc);
        acc = fmaf(av.w, bv.w, acc);
    }
    C[(long)m * N + n] = acc + bias[n];
}

// ---------------- elementwise epilogue --------------------------------------
// C = (C (+bias) (+res)) (relu?) * rowscale        one block per row
__global__ __launch_bounds__(128)
void epilogue(float* __restrict__ C, const float* __restrict__ bias,
              const float* __restrict__ res, const float* __restrict__ rowscale,
              int ncol4, int relu)
{
    long row = blockIdx.x;
    float rs = rowscale ? rowscale[row] : 1.f;
    float4* c = reinterpret_cast<float4*>(C + row * (long)ncol4 * 4);
    const float4* r4 = res ? reinterpret_cast<const float4*>(res + row * (long)ncol4 * 4)
                           : nullptr;
    const float4* b4 = bias ? reinterpret_cast<const float4*>(bias) : nullptr;
    for (int i = threadIdx.x; i < ncol4; i += blockDim.x) {
        float4 v = c[i];
        if (b4) { float4 b = b4[i]; v.x += b.x; v.y += b.y; v.z += b.z; v.w += b.w; }
        if (r4) { float4 r = r4[i]; v.x += r.x; v.y += r.y; v.z += r.z; v.w += r.w; }
        if (relu) {
            v.x = fmaxf(v.x, 0.f); v.y = fmaxf(v.y, 0.f);
            v.z = fmaxf(v.z, 0.f); v.w = fmaxf(v.w, 0.f);
        }
        v.x *= rs; v.y *= rs; v.z *= rs; v.w *= rs;
        c[i] = v;
    }
}

// ---------------- masked-mean aggregate + concat ----------------------------
__global__ void agg_concat(const float* __restrict__ sf,
                           const float* __restrict__ child,
                           const int* __restrict__ nbm,
                           float* __restrict__ cat, int n)
{
    int i = blockIdx.x;
    __shared__ int ms[FAN];
    if (threadIdx.x < FAN) ms[threadIdx.x] = nbm[(long)i * FAN + threadIdx.x];
    __syncthreads();
    float denom = 0.f;
    #pragma unroll
    for (int f = 0; f < FAN; f++) denom += (float)ms[f];
    float inv = 1.f / fmaxf(denom, 1.f);
    for (int c = threadIdx.x; c < CDIM; c += blockDim.x) {
        float acc = 0.f;
        #pragma unroll
        for (int f = 0; f < FAN; f++)
            if (ms[f]) acc += child[((long)i * FAN + f) * CDIM + c];
        cat[(long)i * (2 * CDIM) + c]        = sf[(long)i * CDIM + c];
        cat[(long)i * (2 * CDIM) + CDIM + c] = acc * inv;
    }
}

// ---------------- fused add + LayerNorm -------------------------------------
__global__ __launch_bounds__(128)
void ln_add(const float* __restrict__ x, const float* __restrict__ r,
            const float* __restrict__ g, const float* __restrict__ b,
            float* __restrict__ y)
{
    __shared__ float sm[8];
    long row = blockIdx.x;
    int tid = threadIdx.x;
    float4 v = *reinterpret_cast<const float4*>(x + row * CDIM + tid * 4);
    float4 rv = *reinterpret_cast<const float4*>(r + row * CDIM + tid * 4);
    v.x += rv.x; v.y += rv.y; v.z += rv.z; v.w += rv.w;
    float tot = block_sum(v.x + v.y + v.z + v.w, sm);
    float mean = tot * (1.f / CDIM);
    float dx = v.x - mean, dy = v.y - mean, dz = v.z - mean, dw = v.w - mean;
    float var = block_sum(dx * dx + dy * dy + dz * dz + dw * dw, sm) * (1.f / CDIM);
    float rstd = rsqrtf(var + 1e-5f);
    float4 gv = *reinterpret_cast<const float4*>(g + tid * 4);
    float4 bv = *reinterpret_cast<const float4*>(b + tid * 4);
    float4 o;
    o.x = dx * rstd * gv.x + bv.x;
    o.y = dy * rstd * gv.y + bv.y;
    o.z = dz * rstd * gv.z + bv.z;
    o.w = dw * rstd * gv.w + bv.w;
    *reinterpret_cast<float4*>(y + row * CDIM + tid * 4) = o;
}

// ---------------- register-cached row softmax (1 read + 1 write) -----------
template <int VPT>
__global__ __launch_bounds__(256)
void softmax_reg(float* __restrict__ S, int ncols, float scale)
{
    __shared__ float sm[8];
    long row = blockIdx.x;
    float* p = S + row * (long)ncols;
    int tid = threadIdx.x;
    float v[VPT];
    float mx = -3.0e38f;
    #pragma unroll
    for (int i = 0; i < VPT; i++) {
        v[i] = p[tid + i * 256] * scale;
        mx = fmaxf(mx, v[i]);
    }
    mx = block_max(mx, sm);
    float sum = 0.f;
    #pragma unroll
    for (int i = 0; i < VPT; i++) {
        v[i] = __expf(v[i] - mx);
        sum += v[i];
    }
    sum = block_sum(sum, sm);
    float inv = 1.f / sum;
    #pragma unroll
    for (int i = 0; i < VPT; i++) p[tid + i * 256] = v[i] * inv;
}

// ---------------- host helpers ----------------------------------------------
static inline void tg_tb(const float* A, const float* B, float* C,
                         int M, int N, int K, int lda, int ldb, int ldc,
                         long sA = 0, long sB = 0, long sC = 0, int batch = 1)
{
    dim3 g(N / 128, M / 128, batch);
    tgemm128<true><<<g, 256>>>(A, B, C, M, N, K, lda, ldb, ldc, sA, sB, sC);
}

static inline void tg_nn(const float* A, const float* B, float* C,
                         int M, int N, int K, int lda, int ldb, int ldc,
                         long sA = 0, long sB = 0, long sC = 0, int batch = 1)
{
    dim3 g(N / 128, M / 128, batch);
    tgemm128<false><<<g, 256>>>(A, B, C, M, N, K, lda, ldb, ldc, sA, sB, sC);
}

extern "C" void kernel_launch(void* const* d_in, const int* in_sizes, int n_in,
                              void* d_out, int out_size)
{
    const float* feats0 = (const float*)d_in[0];
    const float* feats1 = (const float*)d_in[1];
    const float* feats2 = (const float*)d_in[2];
    const float* nmask0 = (const float*)d_in[3];
    const float* nmask1 = (const float*)d_in[4];
    const float* nmask2 = (const float*)d_in[5];
    const int*   nbm0   = (const int*)d_in[6];
    const int*   nbm1   = (const int*)d_in[7];
    const float* emb_w  = (const float*)d_in[8];
    const float* emb_b  = (const float*)d_in[9];
    const float* sage_w = (const float*)d_in[10];
    const float* sage_b = (const float*)d_in[11];
    const float* qkv_w  = (const float*)d_in[12];
    const float* qkv_b  = (const float*)d_in[13];
    const float* out_w  = (const float*)d_in[14];
    const float* out_b  = (const float*)d_in[15];
    const float* n1_g   = (const float*)d_in[16];
    const float* n1_b   = (const float*)d_in[17];
    const float* n2_g   = (const float*)d_in[18];
    const float* n2_b   = (const float*)d_in[19];
    const float* ffn_w1 = (const float*)d_in[20];
    const float* ffn_b1 = (const float*)d_in[21];
    const float* ffn_w2 = (const float*)d_in[22];
    const float* ffn_b2 = (const float*)d_in[23];
    const float* cls_w  = (const float*)d_in[24];
    const float* cls_b  = (const float*)d_in[25];
    float* out = (float*)d_out;
    (void)in_sizes; (void)n_in; (void)out_size;

    static float* buf = nullptr;
    if (!buf) cudaGetSymbolAddress((void**)&buf, g_buf);

    float* H2   = buf + OFF_H2;
    float* S1A  = buf + OFF_S1A;
    float* S1B  = buf + OFF_S1B;
    float* S0A  = buf + OFF_S0A;
    float* S0B  = buf + OFF_S0B;
    float* CAT  = buf + OFF_CAT;
    float* TLOC = buf + OFF_TLOC;
    float* HH   = buf + OFF_HH;
    float* QKVb = buf + OFF_QKV;
    float* SCO  = buf + OFF_SCO;
    float* ATO  = buf + OFF_ATO;
    float* HH2  = buf + OFF_HH2;
    float* FFH  = buf + OFF_FFH;

    const float attn_scale = 0.088388347648318447f;  // 1/sqrt(128)

    auto run_block = [&](int li, int n, const float* sf, const float* child,
                         const int* nbm, const float* nmask, float* out_state) {
        // masked-mean aggregation + concat -> CAT [n, 2C]
        agg_concat<<<n, 256>>>(sf, child, nbm, CAT, n);
        // h_local = CAT @ sage_w[li]^T + sage_b[li]
        tg_tb(CAT, sage_w + (long)li * CDIM * 2 * CDIM, TLOC,
              n, CDIM, 2 * CDIM, 2 * CDIM, 2 * CDIM, CDIM);
        epilogue<<<n, 128>>>(TLOC, sage_b + li * CDIM, nullptr, nullptr, CDIM / 4, 0);
        // h = LN(sf + h_local)
        ln_add<<<n, 128>>>(sf, TLOC, n1_g + li * CDIM, n1_b + li * CDIM, HH);
        // qkv = h @ qkv_w^T + qkv_b   [n, 3C]
        tg_tb(HH, qkv_w + (long)li * 3 * CDIM * CDIM, QKVb,
              n, 3 * CDIM, CDIM, CDIM, CDIM, 3 * CDIM);
        epilogue<<<n, 128>>>(QKVb, qkv_b + li * 3 * CDIM, nullptr, nullptr,
                             3 * CDIM / 4, 0);
        // S[h] = Q_h K_h^T  (scale folded into softmax)
        tg_tb(QKVb, QKVb + CDIM, SCO, n, n, DHEAD,
              3 * CDIM, 3 * CDIM, n, DHEAD, DHEAD, (long)n * n, HEADS);
        if (n == 4096)
            softmax_reg<16><<<HEADS * n, 256>>>(SCO, n, attn_scale);
        else
            softmax_reg<1><<<HEADS * n, 256>>>(SCO, n, attn_scale);
        // O[:, h*DH:(h+1)*DH] = P_h @ V_h
        tg_nn(SCO, QKVb + 2 * CDIM, ATO, n, DHEAD, n,
              n, 3 * CDIM, CDIM, (long)n * n, DHEAD, DHEAD, HEADS);
        // attn = O @ out_w^T + out_b
        tg_tb(ATO, out_w + (long)li * CDIM * CDIM, TLOC,
              n, CDIM, CDIM, CDIM, CDIM, CDIM);
        epilogue<<<n, 128>>>(TLOC, out_b + li * CDIM, nullptr, nullptr, CDIM / 4, 0);
        // h2 = LN(h + attn)
        ln_add<<<n, 128>>>(HH, TLOC, n2_g + li * CDIM, n2_b + li * CDIM, HH2);
        // hid = relu(h2 @ w1^T + b1)
        tg_tb(HH2, ffn_w1 + (long)li * 2 * CDIM * CDIM, FFH,
              n, 2 * CDIM, CDIM, CDIM, CDIM, 2 * CDIM);
        epilogue<<<n, 128>>>(FFH, ffn_b1 + li * 2 * CDIM, nullptr, nullptr,
                             2 * CDIM / 4, 1);
        // out_state = (h2 + hid @ w2^T + b2) * nmask
        tg_tb(FFH, ffn_w2 + (long)li * CDIM * 2 * CDIM, out_state,
              n, CDIM, 2 * CDIM, 2 * CDIM, 2 * CDIM, CDIM);
        epilogue<<<n, 128>>>(out_state, ffn_b2 + li * CDIM, HH2, nmask, CDIM / 4, 0);
    };

    // embeddings: state = (feats @ emb_w^T + emb_b) * nmask
    tg_tb(feats2, emb_w, H2, 65536, CDIM, INDIM, INDIM, INDIM, CDIM);
    epilogue<<<65536, 128>>>(H2, emb_b, nullptr, nmask2, CDIM / 4, 0);
    tg_tb(feats1, emb_w, S1A, 4096, CDIM, INDIM, INDIM, INDIM, CDIM);
    epilogue<<<4096, 128>>>(S1A, emb_b, nullptr, nmask1, CDIM / 4, 0);
    tg_tb(feats0, emb_w, S0A, 256, CDIM, INDIM, INDIM, INDIM, CDIM);
    epilogue<<<256, 128>>>(S0A, emb_b, nullptr, nmask0, CDIM / 4, 0);

    // layer 0: depth 1 (uses old s2), then depth 0 (uses OLD s1)
    run_block(0, 4096, S1A, H2,  nbm1, nmask1, S1B);
    run_block(0, 256,  S0A, S1A, nbm0, nmask0, S0B);
    // layer 1: depth 0 (uses updated s1)
    run_block(1, 256,  S0B, S1B, nbm0, nmask0, S0A);

    // classifier (fp32, tiny)
    {
        dim3 b(16, 16), g((NCLS + 15) / 16, (BSEED + 15) / 16);
        sgemm_cls<<<g, b>>>(S0A, cls_w, cls_b, out, BSEED, NCLS, CDIM);
    }
}

// round 4
// speedup vs baseline: 4.0553x; 2.2347x over previous
#include <cuda_runtime.h>
#include <cuda_fp16.h>
#include <mma.h>

using namespace nvcuda;

// ---------------------------------------------------------------------------
// GraphTransformer — fp16 tensor-core GEMMs (fp32 accum), fused elementwise
// ---------------------------------------------------------------------------

#define NLAY 2
#define HEADS 4
#define CDIM 512
#define INDIM 256
#define FAN 16
#define BSEED 256
#define NCLS 47
#define DHEAD 128

// ---------------- scratch (static device memory; no allocations) -----------
constexpr long SZ_H2  = 65536L * 512;
constexpr long SZ_S1  = 4096L * 512;
constexpr long SZ_S0  = 256L * 512;
constexpr long SZ_CAT = 4096L * 1024;
constexpr long SZ_C   = 4096L * 512;
constexpr long SZ_QKV = 4096L * 1536;
constexpr long SZ_SCO = 4L * 4096L * 4096L;
constexpr long SZ_FFH = 4096L * 1024;

constexpr long OFF_H2   = 0;
constexpr long OFF_S1A  = OFF_H2  + SZ_H2;
constexpr long OFF_S1B  = OFF_S1A + SZ_S1;
constexpr long OFF_S0A  = OFF_S1B + SZ_S1;
constexpr long OFF_S0B  = OFF_S0A + SZ_S0;
constexpr long OFF_CAT  = OFF_S0B + SZ_S0;
constexpr long OFF_TLOC = OFF_CAT + SZ_CAT;
constexpr long OFF_HH   = OFF_TLOC + SZ_C;
constexpr long OFF_QKV  = OFF_HH  + SZ_C;
constexpr long OFF_SCO  = OFF_QKV + SZ_QKV;
constexpr long OFF_ATO  = OFF_SCO + SZ_SCO;
constexpr long OFF_HH2  = OFF_ATO + SZ_C;
constexpr long OFF_FFH  = OFF_HH2 + SZ_C;
constexpr long TOTAL_F  = OFF_FFH + SZ_FFH;

__device__ float g_buf[TOTAL_F];

// ---------------- block reductions -----------------------------------------
__device__ __forceinline__ float block_sum(float v, float* sm) {
    int lane = threadIdx.x & 31, w = threadIdx.x >> 5;
    #pragma unroll
    for (int o = 16; o; o >>= 1) v += __shfl_xor_sync(0xffffffffu, v, o);
    if (lane == 0) sm[w] = v;
    __syncthreads();
    float t = 0.f;
    int nw = blockDim.x >> 5;
    for (int i = 0; i < nw; i++) t += sm[i];
    __syncthreads();
    return t;
}

__device__ __forceinline__ float block_max(float v, float* sm) {
    int lane = threadIdx.x & 31, w = threadIdx.x >> 5;
    #pragma unroll
    for (int o = 16; o; o >>= 1) v = fmaxf(v, __shfl_xor_sync(0xffffffffu, v, o));
    if (lane == 0) sm[w] = v;
    __syncthreads();
    float t = -3.0e38f;
    int nw = blockDim.x >> 5;
    for (int i = 0; i < nw; i++) t = fmaxf(t, sm[i]);
    __syncthreads();
    return t;
}

// ---------------- fp16 tensor-core GEMM, BK=32, reg double-buffer ----------
// C = A * op(B).  TB=true: B is [N,K] row-major (C = A B^T).
//                 TB=false: B is [K,N] row-major (C = A B).
// Requires: M % 128 == 0, N % 128 == 0, K % 32 == 0, float4-aligned pointers.
// Operands converted fp32 -> fp16 (RN) at the smem store; fp32 accumulate.
template <bool TB>
__global__ __launch_bounds__(256)
void hgemm128(const float* __restrict__ A, const float* __restrict__ B,
              float* __restrict__ C, int M, int N, int K,
              int lda, int ldb, int ldc, long sA, long sB, long sC)
{
    __shared__ __align__(16) __half As[128][40];      // 128 x 32 (pad 8)
    __shared__ __align__(16) __half Bsm[128 * 40];    // TB: [128][40]; NN: [32][136]

    A += blockIdx.z * sA;  B += blockIdx.z * sB;  C += blockIdx.z * sC;

    const int tid = threadIdx.x;
    const int m0  = blockIdx.y * 128;
    const int n0  = blockIdx.x * 128;
    const int wid = tid >> 5;
    const int wm  = wid >> 2;        // 0..1  (64-row slab)
    const int wn  = wid & 3;         // 0..3  (32-col slab)

    // per-thread load coordinates (4 x float4 per matrix per tile)
    // A / TB-B tile: 128 x 32  -> li = tid + i*256 : r = li>>3, c = (li&7)*4
    // NN-B tile:     32 x 128  -> r = li>>5, c = (li&31)*4
    const int a_r[4] = { (tid + 0) >> 3, (tid + 256) >> 3,
                         (tid + 512) >> 3, (tid + 768) >> 3 };
    const int a_c   = (tid & 7) * 4;
    const int bn_r[4] = { (tid + 0) >> 5, (tid + 256) >> 5,
                          (tid + 512) >> 5, (tid + 768) >> 5 };
    const int bn_c  = (tid & 31) * 4;

    wmma::fragment<wmma::accumulator, 16, 16, 16, float> cf[4][2];
    #pragma unroll
    for (int m = 0; m < 4; m++)
        #pragma unroll
        for (int n = 0; n < 2; n++) wmma::fill_fragment(cf[m][n], 0.f);

    float4 pa[4], pb[4];

    auto ld_tile = [&](int k0, float4* ra, float4* rb) {
        #pragma unroll
        for (int i = 0; i < 4; i++)
            ra[i] = *reinterpret_cast<const float4*>(
                &A[(long)(m0 + a_r[i]) * lda + k0 + a_c]);
        if (TB) {
            #pragma unroll
            for (int i = 0; i < 4; i++)
                rb[i] = *reinterpret_cast<const float4*>(
                    &B[(long)(n0 + a_r[i]) * ldb + k0 + a_c]);
        } else {
            #pragma unroll
            for (int i = 0; i < 4; i++)
                rb[i] = *reinterpret_cast<const float4*>(
                    &B[(long)(k0 + bn_r[i]) * ldb + n0 + bn_c]);
        }
    };

    auto st_tile = [&](const float4* ra, const float4* rb) {
        #pragma unroll
        for (int i = 0; i < 4; i++) {
            __half2* d = reinterpret_cast<__half2*>(&As[a_r[i]][a_c]);
            d[0] = __floats2half2_rn(ra[i].x, ra[i].y);
            d[1] = __floats2half2_rn(ra[i].z, ra[i].w);
        }
        if (TB) {
            __half (*Bt)[40] = reinterpret_cast<__half (*)[40]>(Bsm);
            #pragma unroll
            for (int i = 0; i < 4; i++) {
                __half2* d = reinterpret_cast<__half2*>(&Bt[a_r[i]][a_c]);
                d[0] = __floats2half2_rn(rb[i].x, rb[i].y);
                d[1] = __floats2half2_rn(rb[i].z, rb[i].w);
            }
        } else {
            __half (*Bn)[136] = reinterpret_cast<__half (*)[136]>(Bsm);
            #pragma unroll
            for (int i = 0; i < 4; i++) {
                __half2* d = reinterpret_cast<__half2*>(&Bn[bn_r[i]][bn_c]);
                d[0] = __floats2half2_rn(rb[i].x, rb[i].y);
                d[1] = __floats2half2_rn(rb[i].z, rb[i].w);
            }
        }
    };

    // prologue
    ld_tile(0, pa, pb);
    st_tile(pa, pb);
    __syncthreads();

    for (int k0 = 0; k0 < K; k0 += 32) {
        const bool more = (k0 + 32) < K;
        if (more) ld_tile(k0 + 32, pa, pb);     // prefetch next tile -> regs

        #pragma unroll
        for (int kk = 0; kk < 32; kk += 16) {
            wmma::fragment<wmma::matrix_a, 16, 16, 16, __half,
                           wmma::row_major> af[4];
            #pragma unroll
            for (int m = 0; m < 4; m++)
                wmma::load_matrix_sync(af[m], &As[wm * 64 + m * 16][kk], 40);

            if constexpr (TB) {
                wmma::fragment<wmma::matrix_b, 16, 16, 16, __half,
                               wmma::col_major> bf[2];
                __half (*Bt)[40] = reinterpret_cast<__half (*)[40]>(Bsm);
                #pragma unroll
                for (int n = 0; n < 2; n++)
                    wmma::load_matrix_sync(bf[n], &Bt[wn * 32 + n * 16][kk], 40);
                #pragma unroll
                for (int m = 0; m < 4; m++)
                    #pragma unroll
                    for (int n = 0; n < 2; n++)
                        wmma::mma_sync(cf[m][n], af[m], bf[n], cf[m][n]);
            } else {
                wmma::fragment<wmma::matrix_b, 16, 16, 16, __half,
                               wmma::row_major> bf[2];
                __half (*Bn)[136] = reinterpret_cast<__half (*)[136]>(Bsm);
                #pragma unroll
                for (int n = 0; n < 2; n++)
                    wmma::load_matrix_sync(bf[n], &Bn[kk][wn * 32 + n * 16], 136);
                #pragma unroll
                for (int m = 0; m < 4; m++)
                    #pragma unroll
                    for (int n = 0; n < 2; n++)
                        wmma::mma_sync(cf[m][n], af[m], bf[n], cf[m][n]);
            }
        }
        __syncthreads();
        if (more) {
            st_tile(pa, pb);
            __syncthreads();
        }
    }

    #pragma unroll
    for (int m = 0; m < 4; m++)
        #pragma unroll
        for (int n = 0; n < 2; n++)
            wmma::store_matrix_sync(
                &C[(long)(m0 + wm * 64 + m * 16) * ldc + n0 + wn * 32 + n * 16],
                cf[m][n], ldc, wmma::mem_row_major);
}

// ---------------- fp32 SGEMM (classifier only: N=47) ------------------------
__global__ __launch_bounds__(256)
void sgemm_cls(const float* __restrict__ A, const float* __restrict__ B,
               const float* __restrict__ bias, float* __restrict__ C,
               int M, int N, int K)
{
    int m = blockIdx.y * blockDim.y + threadIdx.y;
    int n = blockIdx.x * blockDim.x + threadIdx.x;
    if (m >= M || n >= N) return;
    const float* a = A + (long)m * K;
    const float* b = B + (long)n * K;
    float acc = 0.f;
    for (int k = 0; k < K; k += 4) {
        float4 av = *reinterpret_cast<const float4*>(a + k);
        float4 bv = *reinterpret_cast<const float4*>(b + k);
        acc = fmaf(av.x, bv.x, acc);
        acc = fmaf(av.y, bv.y, acc);
        acc = fmaf(av.z, bv.z, acc);
        acc = fmaf(av.w, bv.w, acc);
    }
    C[(long)m * N + n] = acc + bias[n];
}

// ---------------- elementwise epilogue --------------------------------------
// C = (C (+bias) (+res)) (relu?) * rowscale        one block per row
__global__ __launch_bounds__(128)
void epilogue(float* __restrict__ C, const float* __restrict__ bias,
              const float* __restrict__ res, const float* __restrict__ rowscale,
              int ncol4, int relu)
{
    long row = blockIdx.x;
    float rs = rowscale ? rowscale[row] : 1.f;
    float4* c = reinterpret_cast<float4*>(C + row * (long)ncol4 * 4);
    const float4* r4 = res ? reinterpret_cast<const float4*>(res + row * (long)ncol4 * 4)
                           : nullptr;
    const float4* b4 = bias ? reinterpret_cast<const float4*>(bias) : nullptr;
    for (int i = threadIdx.x; i < ncol4; i += blockDim.x) {
        float4 v = c[i];
        if (b4) { float4 b = b4[i]; v.x += b.x; v.y += b.y; v.z += b.z; v.w += b.w; }
        if (r4) { float4 r = r4[i]; v.x += r.x; v.y += r.y; v.z += r.z; v.w += r.w; }
        if (relu) {
            v.x = fmaxf(v.x, 0.f); v.y = fmaxf(v.y, 0.f);
            v.z = fmaxf(v.z, 0.f); v.w = fmaxf(v.w, 0.f);
        }
        v.x *= rs; v.y *= rs; v.z *= rs; v.w *= rs;
        c[i] = v;
    }
}

// ---------------- masked-mean aggregate + concat ----------------------------
__global__ void agg_concat(const float* __restrict__ sf,
                           const float* __restrict__ child,
                           const int* __restrict__ nbm,
                           float* __restrict__ cat, int n)
{
    int i = blockIdx.x;
    __shared__ int ms[FAN];
    if (threadIdx.x < FAN) ms[threadIdx.x] = nbm[(long)i * FAN + threadIdx.x];
    __syncthreads();
    float denom = 0.f;
    #pragma unroll
    for (int f = 0; f < FAN; f++) denom += (float)ms[f];
    float inv = 1.f / fmaxf(denom, 1.f);
    for (int c = threadIdx.x; c < CDIM; c += blockDim.x) {
        float acc = 0.f;
        #pragma unroll
        for (int f = 0; f < FAN; f++)
            if (ms[f]) acc += child[((long)i * FAN + f) * CDIM + c];
        cat[(long)i * (2 * CDIM) + c]        = sf[(long)i * CDIM + c];
        cat[(long)i * (2 * CDIM) + CDIM + c] = acc * inv;
    }
}

// ---------------- fused add + LayerNorm -------------------------------------
__global__ __launch_bounds__(128)
void ln_add(const float* __restrict__ x, const float* __restrict__ r,
            const float* __restrict__ g, const float* __restrict__ b,
            float* __restrict__ y)
{
    __shared__ float sm[8];
    long row = blockIdx.x;
    int tid = threadIdx.x;
    float4 v = *reinterpret_cast<const float4*>(x + row * CDIM + tid * 4);
    float4 rv = *reinterpret_cast<const float4*>(r + row * CDIM + tid * 4);
    v.x += rv.x; v.y += rv.y; v.z += rv.z; v.w += rv.w;
    float tot = block_sum(v.x + v.y + v.z + v.w, sm);
    float mean = tot * (1.f / CDIM);
    float dx = v.x - mean, dy = v.y - mean, dz = v.z - mean, dw = v.w - mean;
    float var = block_sum(dx * dx + dy * dy + dz * dz + dw * dw, sm) * (1.f / CDIM);
    float rstd = rsqrtf(var + 1e-5f);
    float4 gv = *reinterpret_cast<const float4*>(g + tid * 4);
    float4 bv = *reinterpret_cast<const float4*>(b + tid * 4);
    float4 o;
    o.x = dx * rstd * gv.x + bv.x;
    o.y = dy * rstd * gv.y + bv.y;
    o.z = dz * rstd * gv.z + bv.z;
    o.w = dw * rstd * gv.w + bv.w;
    *reinterpret_cast<float4*>(y + row * CDIM + tid * 4) = o;
}

// ---------------- register-cached row softmax (1 read + 1 write) -----------
template <int VPT>
__global__ __launch_bounds__(256)
void softmax_reg(float* __restrict__ S, int ncols, float scale)
{
    __shared__ float sm[8];
    long row = blockIdx.x;
    float* p = S + row * (long)ncols;
    int tid = threadIdx.x;
    float v[VPT];
    float mx = -3.0e38f;
    #pragma unroll
    for (int i = 0; i < VPT; i++) {
        v[i] = p[tid + i * 256] * scale;
        mx = fmaxf(mx, v[i]);
    }
    mx = block_max(mx, sm);
    float sum = 0.f;
    #pragma unroll
    for (int i = 0; i < VPT; i++) {
        v[i] = __expf(v[i] - mx);
        sum += v[i];
    }
    sum = block_sum(sum, sm);
    float inv = 1.f / sum;
    #pragma unroll
    for (int i = 0; i < VPT; i++) p[tid + i * 256] = v[i] * inv;
}

// ---------------- host helpers ----------------------------------------------
static inline void tg_tb(const float* A, const float* B, float* C,
                         int M, int N, int K, int lda, int ldb, int ldc,
                         long sA = 0, long sB = 0, long sC = 0, int batch = 1)
{
    dim3 g(N / 128, M / 128, batch);
    hgemm128<true><<<g, 256>>>(A, B, C, M, N, K, lda, ldb, ldc, sA, sB, sC);
}

static inline void tg_nn(const float* A, const float* B, float* C,
                         int M, int N, int K, int lda, int ldb, int ldc,
                         long sA = 0, long sB = 0, long sC = 0, int batch = 1)
{
    dim3 g(N / 128, M / 128, batch);
    hgemm128<false><<<g, 256>>>(A, B, C, M, N, K, lda, ldb, ldc, sA, sB, sC);
}

extern "C" void kernel_launch(void* const* d_in, const int* in_sizes, int n_in,
                              void* d_out, int out_size)
{
    const float* feats0 = (const float*)d_in[0];
    const float* feats1 = (const float*)d_in[1];
    const float* feats2 = (const float*)d_in[2];
    const float* nmask0 = (const float*)d_in[3];
    const float* nmask1 = (const float*)d_in[4];
    const float* nmask2 = (const float*)d_in[5];
    const int*   nbm0   = (const int*)d_in[6];
    const int*   nbm1   = (const int*)d_in[7];
    const float* emb_w  = (const float*)d_in[8];
    const float* emb_b  = (const float*)d_in[9];
    const float* sage_w = (const float*)d_in[10];
    const float* sage_b = (const float*)d_in[11];
    const float* qkv_w  = (const float*)d_in[12];
    const float* qkv_b  = (const float*)d_in[13];
    const float* out_w  = (const float*)d_in[14];
    const float* out_b  = (const float*)d_in[15];
    const float* n1_g   = (const float*)d_in[16];
    const float* n1_b   = (const float*)d_in[17];
    const float* n2_g   = (const float*)d_in[18];
    const float* n2_b   = (const float*)d_in[19];
    const float* ffn_w1 = (const float*)d_in[20];
    const float* ffn_b1 = (const float*)d_in[21];
    const float* ffn_w2 = (const float*)d_in[22];
    const float* ffn_b2 = (const float*)d_in[23];
    const float* cls_w  = (const float*)d_in[24];
    const float* cls_b  = (const float*)d_in[25];
    float* out = (float*)d_out;
    (void)in_sizes; (void)n_in; (void)out_size;

    static float* buf = nullptr;
    if (!buf) cudaGetSymbolAddress((void**)&buf, g_buf);

    float* H2   = buf + OFF_H2;
    float* S1A  = buf + OFF_S1A;
    float* S1B  = buf + OFF_S1B;
    float* S0A  = buf + OFF_S0A;
    float* S0B  = buf + OFF_S0B;
    float* CAT  = buf + OFF_CAT;
    float* TLOC = buf + OFF_TLOC;
    float* HH   = buf + OFF_HH;
    float* QKVb = buf + OFF_QKV;
    float* SCO  = buf + OFF_SCO;
    float* ATO  = buf + OFF_ATO;
    float* HH2  = buf + OFF_HH2;
    float* FFH  = buf + OFF_FFH;

    const float attn_scale = 0.088388347648318447f;  // 1/sqrt(128)

    auto run_block = [&](int li, int n, const float* sf, const float* child,
                         const int* nbm, const float* nmask, float* out_state) {
        // masked-mean aggregation + concat -> CAT [n, 2C]
        agg_concat<<<n, 256>>>(sf, child, nbm, CAT, n);
        // h_local = CAT @ sage_w[li]^T + sage_b[li]
        tg_tb(CAT, sage_w + (long)li * CDIM * 2 * CDIM, TLOC,
              n, CDIM, 2 * CDIM, 2 * CDIM, 2 * CDIM, CDIM);
        epilogue<<<n, 128>>>(TLOC, sage_b + li * CDIM, nullptr, nullptr, CDIM / 4, 0);
        // h = LN(sf + h_local)
        ln_add<<<n, 128>>>(sf, TLOC, n1_g + li * CDIM, n1_b + li * CDIM, HH);
        // qkv = h @ qkv_w^T + qkv_b   [n, 3C]
        tg_tb(HH, qkv_w + (long)li * 3 * CDIM * CDIM, QKVb,
              n, 3 * CDIM, CDIM, CDIM, CDIM, 3 * CDIM);
        epilogue<<<n, 128>>>(QKVb, qkv_b + li * 3 * CDIM, nullptr, nullptr,
                             3 * CDIM / 4, 0);
        // S[h] = Q_h K_h^T  (scale folded into softmax)
        tg_tb(QKVb, QKVb + CDIM, SCO, n, n, DHEAD,
              3 * CDIM, 3 * CDIM, n, DHEAD, DHEAD, (long)n * n, HEADS);
        if (n == 4096)
            softmax_reg<16><<<HEADS * n, 256>>>(SCO, n, attn_scale);
        else
            softmax_reg<1><<<HEADS * n, 256>>>(SCO, n, attn_scale);
        // O[:, h*DH:(h+1)*DH] = P_h @ V_h
        tg_nn(SCO, QKVb + 2 * CDIM, ATO, n, DHEAD, n,
              n, 3 * CDIM, CDIM, (long)n * n, DHEAD, DHEAD, HEADS);
        // attn = O @ out_w^T + out_b
        tg_tb(ATO, out_w + (long)li * CDIM * CDIM, TLOC,
              n, CDIM, CDIM, CDIM, CDIM, CDIM);
        epilogue<<<n, 128>>>(TLOC, out_b + li * CDIM, nullptr, nullptr, CDIM / 4, 0);
        // h2 = LN(h + attn)
        ln_add<<<n, 128>>>(HH, TLOC, n2_g + li * CDIM, n2_b + li * CDIM, HH2);
        // hid = relu(h2 @ w1^T + b1)
        tg_tb(HH2, ffn_w1 + (long)li * 2 * CDIM * CDIM, FFH,
              n, 2 * CDIM, CDIM, CDIM, CDIM, 2 * CDIM);
        epilogue<<<n, 128>>>(FFH, ffn_b1 + li * 2 * CDIM, nullptr, nullptr,
                             2 * CDIM / 4, 1);
        // out_state = (h2 + hid @ w2^T + b2) * nmask
        tg_tb(FFH, ffn_w2 + (long)li * CDIM * 2 * CDIM, out_state,
              n, CDIM, 2 * CDIM, 2 * CDIM, 2 * CDIM, CDIM);
        epilogue<<<n, 128>>>(out_state, ffn_b2 + li * CDIM, HH2, nmask, CDIM / 4, 0);
    };

    // embeddings: state = (feats @ emb_w^T + emb_b) * nmask
    tg_tb(feats2, emb_w, H2, 65536, CDIM, INDIM, INDIM, INDIM, CDIM);
    epilogue<<<65536, 128>>>(H2, emb_b, nullptr, nmask2, CDIM / 4, 0);
    tg_tb(feats1, emb_w, S1A, 4096, CDIM, INDIM, INDIM, INDIM, CDIM);
    epilogue<<<4096, 128>>>(S1A, emb_b, nullptr, nmask1, CDIM / 4, 0);
    tg_tb(feats0, emb_w, S0A, 256, CDIM, INDIM, INDIM, INDIM, CDIM);
    epilogue<<<256, 128>>>(S0A, emb_b, nullptr, nmask0, CDIM / 4, 0);

    // layer 0: depth 1 (uses old s2), then depth 0 (uses OLD s1)
    run_block(0, 4096, S1A, H2,  nbm1, nmask1, S1B);
    run_block(0, 256,  S0A, S1A, nbm0, nmask0, S0B);
    // layer 1: depth 0 (uses updated s1)
    run_block(1, 256,  S0B, S1B, nbm0, nmask0, S0A);

    // classifier (fp32, tiny)
    {
        dim3 b(16, 16), g((NCLS + 15) / 16, (BSEED + 15) / 16);
        sgemm_cls<<<g, b>>>(S0A, cls_w, cls_b, out, BSEED, NCLS, CDIM);
    }
}

// round 9
// speedup vs baseline: 5.0033x; 1.2338x over previous
#include <cuda_runtime.h>
#include <cuda_fp16.h>
#include <cstdint>
#include <mma.h>

using namespace nvcuda;

// ---------------------------------------------------------------------------
// GraphTransformer — fp16-resident operands + wmma GEMM (R4 skeleton),
// fused bias-into-LN, flexible convert/epilogue kernel, fp16 softmax probs.
// No inline PTX (bisect away from the container-killing variant).
// ---------------------------------------------------------------------------

#define NLAY 2
#define HEADS 4
#define CDIM 512
#define INDIM 256
#define FAN 16
#define BSEED 256
#define NCLS 47
#define DHEAD 128

// ---------------- scratch (static device memory; no allocations) -----------
constexpr long OH_F2   = 0;                         // 65536*256
constexpr long OH_F1   = OH_F2  + 65536L*256;       // 4096*256
constexpr long OH_F0   = OH_F1  + 4096L*256;        // 256*256
constexpr long OH_WEMB = OH_F0  + 256L*256;         // 512*256
constexpr long OH_WSAGE= OH_WEMB+ 512L*256;         // 2*512*1024
constexpr long OH_WQKV = OH_WSAGE+2L*512*1024;      // 2*1536*512
constexpr long OH_WOUT = OH_WQKV+ 2L*1536*512;      // 2*512*512
constexpr long OH_WF1  = OH_WOUT+ 2L*512*512;       // 2*1024*512
constexpr long OH_WF2  = OH_WF1 + 2L*1024*512;      // 2*512*1024
constexpr long OH_H2   = OH_WF2 + 2L*512*1024;      // 65536*512
constexpr long OH_S1A  = OH_H2  + 65536L*512;       // 4096*512
constexpr long OH_S1B  = OH_S1A + 4096L*512;
constexpr long OH_S0A  = OH_S1B + 4096L*512;        // 256*512
constexpr long OH_S0B  = OH_S0A + 256L*512;
constexpr long OH_CAT  = OH_S0B + 256L*512;         // 4096*1024
constexpr long OH_HH   = OH_CAT + 4096L*1024;       // 4096*512
constexpr long OH_QKV  = OH_HH  + 4096L*512;        // 4096*1536
constexpr long OH_P    = OH_QKV + 4096L*1536;       // 4*4096*4096
constexpr long OH_ATO  = OH_P   + 4L*4096*4096;     // 4096*512
constexpr long OH_HH2  = OH_ATO + 4096L*512;
constexpr long OH_FFH  = OH_HH2 + 4096L*512;        // 4096*1024
constexpr long TOT_H   = OH_FFH + 4096L*1024;

constexpr long OF_SCO  = 0;                         // 4*4096*4096 (+tmp alias)
constexpr long OF_TLOC = OF_SCO + 4L*4096*4096;     // 4096*512
constexpr long OF_S1A  = OF_TLOC+ 4096L*512;
constexpr long OF_S1B  = OF_S1A + 4096L*512;
constexpr long OF_S0A  = OF_S1B + 4096L*512;        // 256*512
constexpr long OF_S0B  = OF_S0A + 256L*512;
constexpr long OF_HH   = OF_S0B + 256L*512;         // 4096*512
constexpr long OF_HH2  = OF_HH  + 4096L*512;
constexpr long TOT_F   = OF_HH2 + 4096L*512;

__device__ __half g_h[TOT_H];
__device__ float  g_f[TOT_F];

// ---------------- block reductions -----------------------------------------
__device__ __forceinline__ float block_sum(float v, float* sm)
{
    int lane = threadIdx.x & 31, w = threadIdx.x >> 5;
    #pragma unroll
    for (int o = 16; o; o >>= 1) v += __shfl_xor_sync(0xffffffffu, v, o);
    if (lane == 0) sm[w] = v;
    __syncthreads();
    float t = 0.f;
    int nw = blockDim.x >> 5;
    for (int i = 0; i < nw; i++) t += sm[i];
    __syncthreads();
    return t;
}

__device__ __forceinline__ float block_max(float v, float* sm)
{
    int lane = threadIdx.x & 31, w = threadIdx.x >> 5;
    #pragma unroll
    for (int o = 16; o; o >>= 1) v = fmaxf(v, __shfl_xor_sync(0xffffffffu, v, o));
    if (lane == 0) sm[w] = v;
    __syncthreads();
    float t = -3.0e38f;
    int nw = blockDim.x >> 5;
    for (int i = 0; i < nw; i++) t = fmaxf(t, sm[i]);
    __syncthreads();
    return t;
}

// ---------------- fp16-operand wmma GEMM, BK=32, reg double-buffer ----------
// C(fp32) = A * op(B).  TB=true: B is [N,K] row-major (C = A B^T).
//                       TB=false: B is [K,N] row-major (C = A B).
// Requires M%128==0, N%128==0, K%32==0, 16B-aligned rows.
// Batched over blockIdx.z with element strides sA/sB/sC.
template <bool TB>
__global__ __launch_bounds__(256)
void hgemm128(const __half* __restrict__ A, const __half* __restrict__ B,
              float* __restrict__ C, int M, int N, int K,
              int lda, int ldb, int ldc, long sA, long sB, long sC)
{
    __shared__ __half As[128 * 40];     // 128 x 32 halves (pad 8)
    __shared__ __half Bs[128 * 40];     // TB: [128][40]; NN: [32][136]

    A += blockIdx.z * sA;
    B += blockIdx.z * sB;
    C += blockIdx.z * sC;

    const int tid = threadIdx.x;
    const int m0  = blockIdx.y * 128;
    const int n0  = blockIdx.x * 128;
    const int wid = tid >> 5;
    const int wm  = wid >> 2;        // 0..1  (64-row slab)
    const int wn  = wid & 3;         // 0..3  (32-col slab)

    // load coords: tile of 128x32 halves = 512 uint4; 2 per thread.
    // A / TB-B: r = li>>2, c = (li&3)*8.   NN-B (32x128): r = li>>4, c=(li&15)*8
    const int a_r[2] = { (tid + 0) >> 2, (tid + 256) >> 2 };
    const int a_c    = (tid & 3) * 8;
    const int bn_r[2] = { (tid + 0) >> 4, (tid + 256) >> 4 };
    const int bn_c    = (tid & 15) * 8;

    wmma::fragment<wmma::accumulator, 16, 16, 16, float> cf[4][2];
    #pragma unroll
    for (int m = 0; m < 4; m++) {
        #pragma unroll
        for (int n = 0; n < 2; n++) wmma::fill_fragment(cf[m][n], 0.f);
    }

    uint4 pa[2], pb[2];

    auto ld_tile = [&](int k0) {
        #pragma unroll
        for (int i = 0; i < 2; i++) {
            pa[i] = *reinterpret_cast<const uint4*>(
                &A[(long)(m0 + a_r[i]) * lda + k0 + a_c]);
        }
        if (TB) {
            #pragma unroll
            for (int i = 0; i < 2; i++) {
                pb[i] = *reinterpret_cast<const uint4*>(
                    &B[(long)(n0 + a_r[i]) * ldb + k0 + a_c]);
            }
        } else {
            #pragma unroll
            for (int i = 0; i < 2; i++) {
                pb[i] = *reinterpret_cast<const uint4*>(
                    &B[(long)(k0 + bn_r[i]) * ldb + n0 + bn_c]);
            }
        }
    };

    auto st_tile = [&]() {
        #pragma unroll
        for (int i = 0; i < 2; i++)
            *reinterpret_cast<uint4*>(&As[a_r[i] * 40 + a_c]) = pa[i];
        if (TB) {
            #pragma unroll
            for (int i = 0; i < 2; i++)
                *reinterpret_cast<uint4*>(&Bs[a_r[i] * 40 + a_c]) = pb[i];
        } else {
            #pragma unroll
            for (int i = 0; i < 2; i++)
                *reinterpret_cast<uint4*>(&Bs[bn_r[i] * 136 + bn_c]) = pb[i];
        }
    };

    // prologue
    ld_tile(0);
    st_tile();
    __syncthreads();

    for (int k0 = 0; k0 < K; k0 += 32) {
        const bool more = (k0 + 32) < K;
        if (more) ld_tile(k0 + 32);     // prefetch next tile into regs

        #pragma unroll
        for (int kk = 0; kk < 32; kk += 16) {
            wmma::fragment<wmma::matrix_a, 16, 16, 16, __half,
                           wmma::row_major> af[4];
            #pragma unroll
            for (int m = 0; m < 4; m++)
                wmma::load_matrix_sync(af[m],
                    &As[(wm * 64 + m * 16) * 40 + kk], 40);

            if constexpr (TB) {
                wmma::fragment<wmma::matrix_b, 16, 16, 16, __half,
                               wmma::col_major> bf[2];
                #pragma unroll
                for (int n = 0; n < 2; n++)
                    wmma::load_matrix_sync(bf[n],
                        &Bs[(wn * 32 + n * 16) * 40 + kk], 40);
                #pragma unroll
                for (int m = 0; m < 4; m++) {
                    #pragma unroll
                    for (int n = 0; n < 2; n++)
                        wmma::mma_sync(cf[m][n], af[m], bf[n], cf[m][n]);
                }
            } else {
                wmma::fragment<wmma::matrix_b, 16, 16, 16, __half,
                               wmma::row_major> bf[2];
                #pragma unroll
                for (int n = 0; n < 2; n++)
                    wmma::load_matrix_sync(bf[n],
                        &Bs[kk * 136 + wn * 32 + n * 16], 136);
                #pragma unroll
                for (int m = 0; m < 4; m++) {
                    #pragma unroll
                    for (int n = 0; n < 2; n++)
                        wmma::mma_sync(cf[m][n], af[m], bf[n], cf[m][n]);
                }
            }
        }
        __syncthreads();
        if (more) {
            st_tile();
            __syncthreads();
        }
    }

    #pragma unroll
    for (int m = 0; m < 4; m++) {
        #pragma unroll
        for (int n = 0; n < 2; n++)
            wmma::store_matrix_sync(
                &C[(long)(m0 + wm * 64 + m * 16) * ldc + n0 + wn * 32 + n * 16],
                cf[m][n], ldc, wmma::mem_row_major);
    }
}

// ---------------- convert / epilogue kernel ---------------------------------
// o = (Cin (+bias) (+res)) (relu?) * rowscale  -> o16 and/or o32
__global__ __launch_bounds__(128)
void ep(const float* __restrict__ Cin, const float* __restrict__ bias,
        const float* __restrict__ res, const float* __restrict__ rowscale,
        __half* __restrict__ o16, float* __restrict__ o32,
        int ncol4, int relu)
{
    long row = blockIdx.x;
    long base = row * (long)ncol4 * 4;
    float rs = rowscale ? rowscale[row] : 1.f;
    const float4* c4 = reinterpret_cast<const float4*>(Cin + base);
    const float4* r4 = res ? reinterpret_cast<const float4*>(res + base)
                           : (const float4*)0;
    const float4* b4 = bias ? reinterpret_cast<const float4*>(bias)
                            : (const float4*)0;
    for (int i = threadIdx.x; i < ncol4; i += blockDim.x) {
        float4 v = c4[i];
        if (b4) { float4 b = b4[i]; v.x += b.x; v.y += b.y; v.z += b.z; v.w += b.w; }
        if (r4) { float4 r = r4[i]; v.x += r.x; v.y += r.y; v.z += r.z; v.w += r.w; }
        if (relu) {
            v.x = fmaxf(v.x, 0.f); v.y = fmaxf(v.y, 0.f);
            v.z = fmaxf(v.z, 0.f); v.w = fmaxf(v.w, 0.f);
        }
        v.x *= rs; v.y *= rs; v.z *= rs; v.w *= rs;
        if (o32) *reinterpret_cast<float4*>(o32 + base + i * 4) = v;
        if (o16) {
            __half2* d = reinterpret_cast<__half2*>(o16 + base + i * 4);
            d[0] = __floats2half2_rn(v.x, v.y);
            d[1] = __floats2half2_rn(v.z, v.w);
        }
    }
}

// ---------------- fp32 -> fp16 conversion (n % 8 == 0) ----------------------
__global__ void f2h(const float* __restrict__ s, __half* __restrict__ d, long n)
{
    long step = (long)gridDim.x * blockDim.x * 8;
    for (long i = ((long)blockIdx.x * blockDim.x + threadIdx.x) * 8; i < n;
         i += step) {
        float4 a = *reinterpret_cast<const float4*>(s + i);
        float4 b = *reinterpret_cast<const float4*>(s + i + 4);
        __half2 o[4];
        o[0] = __floats2half2_rn(a.x, a.y);
        o[1] = __floats2half2_rn(a.z, a.w);
        o[2] = __floats2half2_rn(b.x, b.y);
        o[3] = __floats2half2_rn(b.z, b.w);
        *reinterpret_cast<uint4*>(d + i) = *reinterpret_cast<uint4*>(o);
    }
}

// ---------------- masked-mean aggregate + concat (fp16) ---------------------
__global__ void agg_concat_h(const __half* __restrict__ sf,
                             const __half* __restrict__ child,
                             const int* __restrict__ nbm,
                             __half* __restrict__ cat, int n)
{
    int i = blockIdx.x;
    __shared__ int ms[FAN];
    if (threadIdx.x < FAN) ms[threadIdx.x] = nbm[(long)i * FAN + threadIdx.x];
    __syncthreads();
    float denom = 0.f;
    #pragma unroll
    for (int f = 0; f < FAN; f++) denom += (float)ms[f];
    float inv = 1.f / fmaxf(denom, 1.f);
    int t = threadIdx.x;   // 256 threads, one half2 (2 cols) each
    const __half2* sf2 = reinterpret_cast<const __half2*>(sf) + (long)i * 256;
    __half2* cat2 = reinterpret_cast<__half2*>(cat) + (long)i * 512;
    float ax = 0.f, ay = 0.f;
    #pragma unroll
    for (int f = 0; f < FAN; f++) {
        if (ms[f]) {
            __half2 v = reinterpret_cast<const __half2*>(child)
                            [((long)i * FAN + f) * 256 + t];
            float2 vf = __half22float2(v);
            ax += vf.x;
            ay += vf.y;
        }
    }
    cat2[t]       = sf2[t];
    cat2[256 + t] = __floats2half2_rn(ax * inv, ay * inv);
}

// ---------------- fused (add + bias) + LayerNorm -> fp16 + fp32 -------------
__global__ __launch_bounds__(128)
void ln_add(const float* __restrict__ x, const float* __restrict__ r,
            const float* __restrict__ bias,
            const float* __restrict__ g, const float* __restrict__ b,
            __half* __restrict__ y16, float* __restrict__ y32)
{
    __shared__ float sm[8];
    long row = blockIdx.x;
    int tid = threadIdx.x;
    float4 v = *reinterpret_cast<const float4*>(x + row * CDIM + tid * 4);
    float4 rv = *reinterpret_cast<const float4*>(r + row * CDIM + tid * 4);
    float4 bi = *reinterpret_cast<const float4*>(bias + tid * 4);
    v.x += rv.x + bi.x; v.y += rv.y + bi.y;
    v.z += rv.z + bi.z; v.w += rv.w + bi.w;
    float tot = block_sum(v.x + v.y + v.z + v.w, sm);
    float mean = tot * (1.f / CDIM);
    float dx = v.x - mean, dy = v.y - mean, dz = v.z - mean, dw = v.w - mean;
    float var = block_sum(dx * dx + dy * dy + dz * dz + dw * dw, sm) * (1.f / CDIM);
    float rstd = rsqrtf(var + 1e-5f);
    float4 gv = *reinterpret_cast<const float4*>(g + tid * 4);
    float4 bv = *reinterpret_cast<const float4*>(b + tid * 4);
    float4 o;
    o.x = dx * rstd * gv.x + bv.x;
    o.y = dy * rstd * gv.y + bv.y;
    o.z = dz * rstd * gv.z + bv.z;
    o.w = dw * rstd * gv.w + bv.w;
    *reinterpret_cast<float4*>(y32 + row * CDIM + tid * 4) = o;
    __half2 h0 = __floats2half2_rn(o.x, o.y);
    __half2 h1 = __floats2half2_rn(o.z, o.w);
    *reinterpret_cast<__half2*>(y16 + row * CDIM + tid * 4) = h0;
    *reinterpret_cast<__half2*>(y16 + row * CDIM + tid * 4 + 2) = h1;
}

// ---------------- softmax: fp32 scores -> fp16 probs ------------------------
template <int VPT>
__global__ __launch_bounds__(256)
void softmax_h(const float* __restrict__ S, __half* __restrict__ P,
               int ncols, float scale)
{
    __shared__ float sm[8];
    long row = blockIdx.x;
    const float* p = S + row * (long)ncols;
    __half* q = P + row * (long)ncols;
    int tid = threadIdx.x;
    float v[VPT];
    float mx = -3.0e38f;
    #pragma unroll
    for (int i = 0; i < VPT; i++) {
        v[i] = p[tid + i * 256] * scale;
        mx = fmaxf(mx, v[i]);
    }
    mx = block_max(mx, sm);
    float sum = 0.f;
    #pragma unroll
    for (int i = 0; i < VPT; i++) {
        v[i] = __expf(v[i] - mx);
        sum += v[i];
    }
    sum = block_sum(sum, sm);
    float inv = 1.f / sum;
    #pragma unroll
    for (int i = 0; i < VPT; i++) q[tid + i * 256] = __float2half(v[i] * inv);
}

// ---------------- fp32 SGEMM (classifier only: N=47) ------------------------
__global__ __launch_bounds__(256)
void sgemm_cls(const float* __restrict__ A, const float* __restrict__ B,
               const float* __restrict__ bias, float* __restrict__ C,
               int M, int N, int K)
{
    int m = blockIdx.y * blockDim.y + threadIdx.y;
    int n = blockIdx.x * blockDim.x + threadIdx.x;
    if (m >= M || n >= N) return;
    const float* a = A + (long)m * K;
    const float* b = B + (long)n * K;
    float acc = 0.f;
    for (int k = 0; k < K; k += 4) {
        float4 av = *reinterpret_cast<const float4*>(a + k);
        float4 bv = *reinterpret_cast<const float4*>(b + k);
        acc = fmaf(av.x, bv.x, acc);
        acc = fmaf(av.y, bv.y, acc);
        acc = fmaf(av.z, bv.z, acc);
        acc = fmaf(av.w, bv.w, acc);
    }
    C[(long)m * N + n] = acc + bias[n];
}

// ---------------- host helpers ----------------------------------------------
static void hg_tb(const __half* A, const __half* B, float* C,
                  int M, int N, int K, int lda, int ldb, int ldc,
                  long sA, long sB, long sC, int batch)
{
    dim3 g(N / 128, M / 128, batch);
    hgemm128<true><<<g, 256>>>(A, B, C, M, N, K, lda, ldb, ldc, sA, sB, sC);
}

static void hg_nn(const __half* A, const __half* B, float* C,
                  int M, int N, int K, int lda, int ldb, int ldc,
                  long sA, long sB, long sC, int batch)
{
    dim3 g(N / 128, M / 128, batch);
    hgemm128<false><<<g, 256>>>(A, B, C, M, N, K, lda, ldb, ldc, sA, sB, sC);
}

extern "C" void kernel_launch(void* const* d_in, const int* in_sizes, int n_in,
                              void* d_out, int out_size)
{
    const float* feats0 = (const float*)d_in[0];
    const float* feats1 = (const float*)d_in[1];
    const float* feats2 = (const float*)d_in[2];
    const float* nmask0 = (const float*)d_in[3];
    const float* nmask1 = (const float*)d_in[4];
    const float* nmask2 = (const float*)d_in[5];
    const int*   nbm0   = (const int*)d_in[6];
    const int*   nbm1   = (const int*)d_in[7];
    const float* emb_w  = (const float*)d_in[8];
    const float* emb_b  = (const float*)d_in[9];
    const float* sage_w = (const float*)d_in[10];
    const float* sage_b = (const float*)d_in[11];
    const float* qkv_w  = (const float*)d_in[12];
    const float* qkv_b  = (const float*)d_in[13];
    const float* out_w  = (const float*)d_in[14];
    const float* out_b  = (const float*)d_in[15];
    const float* n1_g   = (const float*)d_in[16];
    const float* n1_b   = (const float*)d_in[17];
    const float* n2_g   = (const float*)d_in[18];
    const float* n2_b   = (const float*)d_in[19];
    const float* ffn_w1 = (const float*)d_in[20];
    const float* ffn_b1 = (const float*)d_in[21];
    const float* ffn_w2 = (const float*)d_in[22];
    const float* ffn_b2 = (const float*)d_in[23];
    const float* cls_w  = (const float*)d_in[24];
    const float* cls_b  = (const float*)d_in[25];
    float* out = (float*)d_out;
    (void)in_sizes; (void)n_in; (void)out_size;

    static __half* bh = 0;
    static float*  bf = 0;
    if (!bh) cudaGetSymbolAddress((void**)&bh, g_h);
    if (!bf) cudaGetSymbolAddress((void**)&bf, g_f);

    __half* F2h  = bh + OH_F2;
    __half* F1h  = bh + OH_F1;
    __half* F0h  = bh + OH_F0;
    __half* Wemb = bh + OH_WEMB;
    __half* Wsage= bh + OH_WSAGE;
    __half* Wqkv = bh + OH_WQKV;
    __half* Wout = bh + OH_WOUT;
    __half* Wf1  = bh + OH_WF1;
    __half* Wf2  = bh + OH_WF2;
    __half* H2h  = bh + OH_H2;
    __half* S1Ah = bh + OH_S1A;
    __half* S1Bh = bh + OH_S1B;
    __half* S0Ah = bh + OH_S0A;
    __half* S0Bh = bh + OH_S0B;
    __half* CATh = bh + OH_CAT;
    __half* HHh  = bh + OH_HH;
    __half* QKVh = bh + OH_QKV;
    __half* Ph   = bh + OH_P;
    __half* ATOh = bh + OH_ATO;
    __half* HH2h = bh + OH_HH2;
    __half* FFHh = bh + OH_FFH;

    float* SCOf  = bf + OF_SCO;     // also: big fp32 GEMM-output scratch
    float* TLOCf = bf + OF_TLOC;
    float* S1Af  = bf + OF_S1A;
    float* S1Bf  = bf + OF_S1B;
    float* S0Af  = bf + OF_S0A;
    float* S0Bf  = bf + OF_S0B;
    float* HHf   = bf + OF_HH;
    float* HH2f  = bf + OF_HH2;

    const float attn_scale = 0.088388347648318447f;  // 1/sqrt(128)

    // ---- fp32 -> fp16 conversions (inputs + weights) ----
    f2h<<<1024, 256>>>(feats2, F2h, 65536L * 256);
    f2h<<<256, 256>>>(feats1, F1h, 4096L * 256);
    f2h<<<32, 256>>>(feats0, F0h, 256L * 256);
    f2h<<<64, 256>>>(emb_w, Wemb, 512L * 256);
    f2h<<<256, 256>>>(sage_w, Wsage, 2L * 512 * 1024);
    f2h<<<256, 256>>>(qkv_w, Wqkv, 2L * 1536 * 512);
    f2h<<<128, 256>>>(out_w, Wout, 2L * 512 * 512);
    f2h<<<256, 256>>>(ffn_w1, Wf1, 2L * 1024 * 512);
    f2h<<<256, 256>>>(ffn_w2, Wf2, 2L * 512 * 1024);

    // ---- embeddings: state = (feats @ emb_w^T + emb_b) * nmask ----
    hg_tb(F2h, Wemb, SCOf, 65536, CDIM, INDIM, INDIM, INDIM, CDIM, 0, 0, 0, 1);
    ep<<<65536, 128>>>(SCOf, emb_b, 0, nmask2, H2h, 0, CDIM / 4, 0);
    hg_tb(F1h, Wemb, SCOf, 4096, CDIM, INDIM, INDIM, INDIM, CDIM, 0, 0, 0, 1);
    ep<<<4096, 128>>>(SCOf, emb_b, 0, nmask1, S1Ah, S1Af, CDIM / 4, 0);
    hg_tb(F0h, Wemb, SCOf, 256, CDIM, INDIM, INDIM, INDIM, CDIM, 0, 0, 0, 1);
    ep<<<256, 128>>>(SCOf, emb_b, 0, nmask0, S0Ah, S0Af, CDIM / 4, 0);

    auto run_block = [&](int li, int n, const __half* sfh, const float* sff,
                         const __half* childh, const int* nbm,
                         const float* nmask, __half* outh, float* outf) {
        // aggregate + concat -> CAT [n, 2C] fp16
        agg_concat_h<<<n, 256>>>(sfh, childh, nbm, CATh, n);
        // h_local = CAT @ sage_w^T -> TLOC fp32 (sage bias folded into LN)
        hg_tb(CATh, Wsage + (long)li * CDIM * 2 * CDIM, TLOCf,
              n, CDIM, 2 * CDIM, 2 * CDIM, 2 * CDIM, CDIM, 0, 0, 0, 1);
        // h = LN(sf + h_local + sage_b) -> HH (16+32)
        ln_add<<<n, 128>>>(sff, TLOCf, sage_b + li * CDIM,
                           n1_g + li * CDIM, n1_b + li * CDIM, HHh, HHf);
        // qkv = h @ qkv_w^T (fp32 tmp in SCO) -> +bias -> QKV fp16
        hg_tb(HHh, Wqkv + (long)li * 3 * CDIM * CDIM, SCOf,
              n, 3 * CDIM, CDIM, CDIM, CDIM, 3 * CDIM, 0, 0, 0, 1);
        ep<<<n, 128>>>(SCOf, qkv_b + li * 3 * CDIM, 0, 0, QKVh, 0,
                       3 * CDIM / 4, 0);
        // S = Q K^T per head -> fp32 scores (SCO)
        hg_tb(QKVh, QKVh + CDIM, SCOf,
              n, n, DHEAD, 3 * CDIM, 3 * CDIM, n,
              DHEAD, DHEAD, (long)n * n, HEADS);
        // softmax (scale folded) -> fp16 probs
        if (n == 4096) {
            softmax_h<16><<<HEADS * n, 256>>>(SCOf, Ph, n, attn_scale);
        } else {
            softmax_h<1><<<HEADS * n, 256>>>(SCOf, Ph, n, attn_scale);
        }
        // O = P V per head -> fp32 tmp (TLOC) -> fp16 ATO
        hg_nn(Ph, QKVh + 2 * CDIM, TLOCf,
              n, DHEAD, n, n, 3 * CDIM, CDIM,
              (long)n * n, DHEAD, DHEAD, HEADS);
        ep<<<n, 128>>>(TLOCf, 0, 0, 0, ATOh, 0, CDIM / 4, 0);
        // attn = O @ out_w^T -> TLOC fp32 (out bias folded into LN)
        hg_tb(ATOh, Wout + (long)li * CDIM * CDIM, TLOCf,
              n, CDIM, CDIM, CDIM, CDIM, CDIM, 0, 0, 0, 1);
        // h2 = LN(h + attn + out_b) -> HH2 (16+32)
        ln_add<<<n, 128>>>(HHf, TLOCf, out_b + li * CDIM,
                           n2_g + li * CDIM, n2_b + li * CDIM, HH2h, HH2f);
        // hid = relu(h2 @ w1^T + b1) -> FFH fp16
        hg_tb(HH2h, Wf1 + (long)li * 2 * CDIM * CDIM, SCOf,
              n, 2 * CDIM, CDIM, CDIM, CDIM, 2 * CDIM, 0, 0, 0, 1);
        ep<<<n, 128>>>(SCOf, ffn_b1 + li * 2 * CDIM, 0, 0, FFHh, 0,
                       2 * CDIM / 4, 1);
        // state = (h2 + hid @ w2^T + b2) * nmask -> (16+32)
        hg_tb(FFHh, Wf2 + (long)li * CDIM * 2 * CDIM, SCOf,
              n, CDIM, 2 * CDIM, 2 * CDIM, 2 * CDIM, CDIM, 0, 0, 0, 1);
        ep<<<n, 128>>>(SCOf, ffn_b2 + li * CDIM, HH2f, nmask, outh, outf,
                       CDIM / 4, 0);
    };

    // layer 0: depth 1 (child = s2), then depth 0 (child = OLD s1)
    run_block(0, 4096, S1Ah, S1Af, H2h, nbm1, nmask1, S1Bh, S1Bf);
    run_block(0, 256, S0Ah, S0Af, S1Ah, nbm0, nmask0, S0Bh, S0Bf);
    // layer 1: depth 0 (child = updated s1)
    run_block(1, 256, S0Bh, S0Bf, S1Bh, nbm0, nmask0, S0Ah, S0Af);

    // classifier (fp32, tiny) on fp32 state copy
    {
        dim3 b(16, 16);
        dim3 g((NCLS + 15) / 16, (BSEED + 15) / 16);
        sgemm_cls<<<g, b>>>(S0Af, cls_w, cls_b, out, BSEED, NCLS, CDIM);
    }
}